// round 1
// baseline (speedup 1.0000x reference)
#include <cuda_runtime.h>
#include <cuda_bf16.h>
#include <math.h>

#define N_NODES 20000
#define E_EDGES 320000
#define B_BATCH 128
#define IN_F    25
#define DIM     64
#define H_HEADS 8
#define ETOT    (E_EDGES + N_NODES)

#define NEG_INF (__int_as_float(0xff800000))

// ---------------- scratch (device globals; no runtime allocation) ----------------
__device__ float g_h0[N_NODES * DIM];
__device__ float g_xh[(size_t)N_NODES * H_HEADS * DIM];    // 41 MB
__device__ float g_as[N_NODES * H_HEADS];
__device__ float g_ad[N_NODES * H_HEADS];
__device__ int   g_off[N_NODES + 1];
__device__ int   g_pos[N_NODES];
__device__ int   g_esrc[ETOT];
__device__ float g_aggr[(size_t)N_NODES * H_HEADS * DIM];  // 41 MB
__device__ float g_out[N_NODES * DIM];
__device__ int   g_boff[B_BATCH + 1];
__device__ float g_hst[B_BATCH * DIM];
__device__ float g_cst[B_BATCH * DIM];
__device__ float g_qstar[B_BATCH * 2 * DIM];
__device__ int   g_is64[2];   // [0]=edge_index is int64, [1]=batch is int64

// ---------------- dtype detection (int32 vs int64 arrays) ----------------
// int64 little-endian with values < 2^31 => every odd 32-bit word is 0.
__global__ void k_detect(const int* ei32, const int* bt32) {
    int t = threadIdx.x;  // 256 threads
    int nz = (ei32[2 * t + 1] != 0) ? 1 : 0;
    int any_e = __syncthreads_or(nz);
    // batch is sorted; probe mid-array where int32 values are surely nonzero
    int nzb = (bt32[10000 + 2 * t + 1] != 0) ? 1 : 0;
    int any_b = __syncthreads_or(nzb);
    if (t == 0) { g_is64[0] = any_e ? 0 : 1; g_is64[1] = any_b ? 0 : 1; }
}

__device__ __forceinline__ int ld_idx(const void* p, long i, int is64) {
    return is64 ? (int)((const long long*)p)[i] : ((const int*)p)[i];
}

// ---------------- h0 = relu(x @ W0 + b0) ----------------
__global__ void k_lin0(const float* __restrict__ x, const float* __restrict__ W0,
                       const float* __restrict__ b0) {
    __shared__ float sW[IN_F * DIM];
    __shared__ float sb[DIM];
    int tid = threadIdx.x;
    for (int i = tid; i < IN_F * DIM; i += 256) sW[i] = W0[i];
    if (tid < DIM) sb[tid] = b0[tid];
    __syncthreads();
    int idx = blockIdx.x * 256 + tid;
    if (idx < N_NODES * DIM) {
        int n = idx >> 6, c = idx & 63;
        float acc = sb[c];
        const float* xr = &x[n * IN_F];
        #pragma unroll
        for (int k = 0; k < IN_F; k++) acc += xr[k] * sW[k * DIM + c];
        g_h0[idx] = fmaxf(acc, 0.f);
    }
}

// ---------------- xh = h0 @ Wg  (+ fused a_s/a_d per-head dots) ----------------
// grid (8 heads, 313 row-tiles), 256 threads, BM=BN=K=64
__global__ void k_gemm_xh(const float* __restrict__ Wg, const float* __restrict__ att_src,
                          const float* __restrict__ att_dst) {
    const int h  = blockIdx.x;
    const int m0 = blockIdx.y * 64;
    const int tid = threadIdx.x;
    const int tx = tid & 15, ty = tid >> 4;
    __shared__ float Ast[64][68];  // A transposed: Ast[k][m]
    __shared__ float Bs[64][68];

    #pragma unroll
    for (int l = 0; l < 16; l++) {
        int lin = tid + l * 256;
        int r = lin >> 6, k = lin & 63;
        int row = m0 + r;
        Ast[k][r] = (row < N_NODES) ? g_h0[row * 64 + k] : 0.f;
    }
    #pragma unroll
    for (int l = 0; l < 16; l++) {
        int lin = tid + l * 256;
        int k = lin >> 6, n = lin & 63;
        Bs[k][n] = Wg[k * 512 + h * 64 + n];
    }
    __syncthreads();

    float acc[4][4] = {};
    #pragma unroll
    for (int k = 0; k < 64; k++) {
        float4 a = *(const float4*)&Ast[k][ty * 4];
        float4 b = *(const float4*)&Bs[k][tx * 4];
        float av[4] = {a.x, a.y, a.z, a.w};
        float bv[4] = {b.x, b.y, b.z, b.w};
        #pragma unroll
        for (int i = 0; i < 4; i++)
            #pragma unroll
            for (int j = 0; j < 4; j++) acc[i][j] += av[i] * bv[j];
    }

    float as4[4], ad4[4];
    #pragma unroll
    for (int j = 0; j < 4; j++) {
        as4[j] = att_src[h * 64 + tx * 4 + j];
        ad4[j] = att_dst[h * 64 + tx * 4 + j];
    }
    #pragma unroll
    for (int i = 0; i < 4; i++) {
        int row = m0 + ty * 4 + i;
        float ps = 0.f, pd = 0.f;
        if (row < N_NODES) {
            float4 c = make_float4(acc[i][0], acc[i][1], acc[i][2], acc[i][3]);
            *(float4*)&g_xh[(size_t)row * 512 + h * 64 + tx * 4] = c;
            #pragma unroll
            for (int j = 0; j < 4; j++) { ps += acc[i][j] * as4[j]; pd += acc[i][j] * ad4[j]; }
        }
        #pragma unroll
        for (int off = 8; off; off >>= 1) {
            ps += __shfl_down_sync(0xffffffffu, ps, off);
            pd += __shfl_down_sync(0xffffffffu, pd, off);
        }
        if (tx == 0 && row < N_NODES) {
            g_as[row * 8 + h] = ps;
            g_ad[row * 8 + h] = pd;
        }
    }
}

// ---------------- CSR build (by dst, incl. self-loops) ----------------
__global__ void k_deg_init() {
    int i = blockIdx.x * 256 + threadIdx.x;
    if (i <= N_NODES) g_off[i] = (i == 0) ? 0 : 1;  // self-loop per node
}
__global__ void k_hist(const void* ei) {
    int e = blockIdx.x * 256 + threadIdx.x;
    if (e < E_EDGES) {
        int dst = ld_idx(ei, (long)E_EDGES + e, g_is64[0]);
        atomicAdd(&g_off[dst + 1], 1);
    }
}
__global__ void k_scan() {  // 1 block, 1024 threads: inclusive scan of g_off[0..N]
    __shared__ int partial[1024];
    const int total = N_NODES + 1;
    const int per = (total + 1023) / 1024;
    int t = threadIdx.x;
    int beg = t * per, end = min(beg + per, total);
    int s = 0;
    for (int i = beg; i < end; i++) s += g_off[i];
    partial[t] = s;
    __syncthreads();
    for (int d = 1; d < 1024; d <<= 1) {
        int v = (t >= d) ? partial[t - d] : 0;
        __syncthreads();
        partial[t] += v;
        __syncthreads();
    }
    int run = (t == 0) ? 0 : partial[t - 1];
    for (int i = beg; i < end; i++) { run += g_off[i]; g_off[i] = run; }
}
__global__ void k_pos() {
    int i = blockIdx.x * 256 + threadIdx.x;
    if (i < N_NODES) g_pos[i] = g_off[i];
}
__global__ void k_scatter(const void* ei) {
    int t = blockIdx.x * 256 + threadIdx.x;
    int is64 = g_is64[0];
    if (t < E_EDGES) {
        int src = ld_idx(ei, t, is64);
        int dst = ld_idx(ei, (long)E_EDGES + t, is64);
        int slot = atomicAdd(&g_pos[dst], 1);
        g_esrc[slot] = src;
    } else if (t < E_EDGES + N_NODES) {
        int n = t - E_EDGES;
        int slot = atomicAdd(&g_pos[n], 1);
        g_esrc[slot] = n;  // self-loop
    }
}

// ---------------- per-dst online softmax + aggregation, fused relu(+bg) ----------------
// grid 20000 blocks, 128 threads: head = tid>>4, 4 channels per thread
__global__ void k_agg(const float* __restrict__ bg) {
    int nid = blockIdx.x;
    int tid = threadIdx.x;
    int h = tid >> 4, c0 = (tid & 15) << 2;
    __shared__ float s_ad[8];
    if (tid < 8) s_ad[tid] = g_ad[nid * 8 + tid];
    __syncthreads();
    float adh = s_ad[h];
    int beg = g_off[nid], end = g_off[nid + 1];
    float m = NEG_INF, s = 0.f;
    float a0 = 0.f, a1 = 0.f, a2 = 0.f, a3 = 0.f;
    for (int j = beg; j < end; j++) {
        int src = g_esrc[j];
        float e = g_as[src * 8 + h] + adh;
        e = (e > 0.f) ? e : 0.2f * e;            // leaky_relu 0.2
        float mn = fmaxf(m, e);
        float wo = __expf(m - mn);
        float we = __expf(e - mn);
        const float4 xv = *(const float4*)&g_xh[(size_t)src * 512 + h * 64 + c0];
        s  = s  * wo + we;
        a0 = a0 * wo + we * xv.x;
        a1 = a1 * wo + we * xv.y;
        a2 = a2 * wo + we * xv.z;
        a3 = a3 * wo + we * xv.w;
        m = mn;
    }
    float inv = 1.f / s;
    const float4 bgv = *(const float4*)&bg[h * 64 + c0];
    float4 o;
    o.x = fmaxf(a0 * inv + bgv.x, 0.f);
    o.y = fmaxf(a1 * inv + bgv.y, 0.f);
    o.z = fmaxf(a2 * inv + bgv.z, 0.f);
    o.w = fmaxf(a3 * inv + bgv.w, 0.f);
    *(float4*)&g_aggr[(size_t)nid * 512 + h * 64 + c0] = o;
}

// ---------------- out = relu(aggr @ Wh + bh)  M=20000 N=64 K=512 ----------------
__global__ void k_gemm_out(const float* __restrict__ Wh, const float* __restrict__ bh) {
    const int m0 = blockIdx.x * 64;
    const int tid = threadIdx.x;
    const int tx = tid & 15, ty = tid >> 4;
    __shared__ float Ast[64][68];
    __shared__ float Bs[64][68];
    float acc[4][4] = {};
    for (int kk = 0; kk < 512; kk += 64) {
        #pragma unroll
        for (int l = 0; l < 16; l++) {
            int lin = tid + l * 256;
            int r = lin >> 6, k = lin & 63;
            int row = m0 + r;
            Ast[k][r] = (row < N_NODES) ? g_aggr[(size_t)row * 512 + kk + k] : 0.f;
        }
        #pragma unroll
        for (int l = 0; l < 16; l++) {
            int lin = tid + l * 256;
            int k = lin >> 6, n = lin & 63;
            Bs[k][n] = Wh[(kk + k) * 64 + n];
        }
        __syncthreads();
        #pragma unroll
        for (int k = 0; k < 64; k++) {
            float4 a = *(const float4*)&Ast[k][ty * 4];
            float4 b = *(const float4*)&Bs[k][tx * 4];
            float av[4] = {a.x, a.y, a.z, a.w};
            float bv[4] = {b.x, b.y, b.z, b.w};
            #pragma unroll
            for (int i = 0; i < 4; i++)
                #pragma unroll
                for (int j = 0; j < 4; j++) acc[i][j] += av[i] * bv[j];
        }
        __syncthreads();
    }
    float bh4[4];
    #pragma unroll
    for (int j = 0; j < 4; j++) bh4[j] = bh[tx * 4 + j];
    #pragma unroll
    for (int i = 0; i < 4; i++) {
        int row = m0 + ty * 4 + i;
        if (row < N_NODES) {
            float4 o;
            o.x = fmaxf(acc[i][0] + bh4[0], 0.f);
            o.y = fmaxf(acc[i][1] + bh4[1], 0.f);
            o.z = fmaxf(acc[i][2] + bh4[2], 0.f);
            o.w = fmaxf(acc[i][3] + bh4[3], 0.f);
            *(float4*)&g_out[row * 64 + tx * 4] = o;
        }
    }
}

// ---------------- batch segment boundaries (binary search; robust to empty) ----------------
__global__ void k_boff(const void* bt) {
    int t = blockIdx.x * 256 + threadIdx.x;
    if (t <= B_BATCH) {
        int is64 = g_is64[1];
        int lo = 0, hi = N_NODES;
        while (lo < hi) {
            int mid = (lo + hi) >> 1;
            int v = ld_idx(bt, mid, is64);
            if (v < t) lo = mid + 1; else hi = mid;
        }
        g_boff[t] = lo;
    }
}

__global__ void k_zero_s2s() {
    int t = blockIdx.x * 256 + threadIdx.x;
    if (t < B_BATCH * 2 * DIM) g_qstar[t] = 0.f;
    if (t < B_BATCH * DIM) { g_hst[t] = 0.f; g_cst[t] = 0.f; }
}

__device__ __forceinline__ float sigmoidf_(float x) { return 1.f / (1.f + __expf(-x)); }

// ---------------- LSTM cell: 128 blocks, 256 threads (one per gate output) ----------------
__global__ void k_lstm(const float* __restrict__ W_ih, const float* __restrict__ W_hh,
                       const float* __restrict__ b_ih, const float* __restrict__ b_hh) {
    int b = blockIdx.x, tid = threadIdx.x;
    __shared__ float qs[128], hs[64], gsh[256];
    if (tid < 128) qs[tid] = g_qstar[b * 128 + tid];
    if (tid >= 128 && tid < 192) hs[tid - 128] = g_hst[b * 64 + tid - 128];
    __syncthreads();
    float acc = b_ih[tid] + b_hh[tid];
    const float* wi = &W_ih[tid * 128];
    #pragma unroll 8
    for (int k = 0; k < 128; k++) acc += qs[k] * wi[k];
    const float* wh = &W_hh[tid * 64];
    #pragma unroll 8
    for (int k = 0; k < 64; k++) acc += hs[k] * wh[k];
    gsh[tid] = acc;
    __syncthreads();
    if (tid < 64) {
        float ig = sigmoidf_(gsh[tid]);
        float fg = sigmoidf_(gsh[64 + tid]);
        float gg = tanhf(gsh[128 + tid]);
        float og = sigmoidf_(gsh[192 + tid]);
        float cv = fg * g_cst[b * 64 + tid] + ig * gg;
        float hv = og * tanhf(cv);
        g_cst[b * 64 + tid] = cv;
        g_hst[b * 64 + tid] = hv;
    }
}

// ---------------- Set2Set attention: 128 blocks, 256 threads (4 node-lanes x 64ch) ----------------
__global__ void k_s2s_att() {
    int b = blockIdx.x;
    int tid = threadIdx.x;
    int grp = tid >> 6;     // 0..3
    int c = tid & 63;
    __shared__ float qsm[64];
    __shared__ float wred[8];
    __shared__ float gm[4], gs[4], gr[4][64];
    if (tid < 64) qsm[tid] = g_hst[b * 64 + tid];
    __syncthreads();
    int beg = g_boff[b], end = g_boff[b + 1];
    int cnt = end - beg;
    int iters = (cnt + 3) >> 2;
    float m = NEG_INF, s = 0.f, racc = 0.f;
    for (int it = 0; it < iters; it++) {
        int i = beg + it * 4 + grp;
        bool valid = (i < end);
        float v = valid ? g_out[(size_t)i * 64 + c] : 0.f;
        float p = v * qsm[c];
        #pragma unroll
        for (int off = 16; off; off >>= 1) p += __shfl_down_sync(0xffffffffu, p, off);
        if ((tid & 31) == 0) wred[tid >> 5] = p;
        __syncthreads();
        float e = wred[grp * 2] + wred[grp * 2 + 1];
        __syncthreads();
        if (valid) {
            float mn = fmaxf(m, e);
            float wo = __expf(m - mn);
            float we = __expf(e - mn);
            s = s * wo + we;
            racc = racc * wo + we * v;
            m = mn;
        }
    }
    if (c == 0) { gm[grp] = m; gs[grp] = s; }
    gr[grp][c] = racc;
    __syncthreads();
    if (tid < 64) {
        float M = NEG_INF;
        #pragma unroll
        for (int g = 0; g < 4; g++) M = fmaxf(M, gm[g]);
        float S = 0.f, R = 0.f;
        #pragma unroll
        for (int g = 0; g < 4; g++) {
            float w = (gm[g] == NEG_INF) ? 0.f : __expf(gm[g] - M);
            S += gs[g] * w;
            R += gr[g][tid] * w;
        }
        float r = (S > 0.f) ? (R / S) : 0.f;
        g_qstar[b * 128 + tid] = qsm[tid];
        g_qstar[b * 128 + 64 + tid] = r;
    }
}

// ---------------- final MLP: y = relu(q_star@W1+b1)@W2+b2 ----------------
__global__ void k_final(const float* __restrict__ W1, const float* __restrict__ b1,
                        const float* __restrict__ W2, const float* __restrict__ b2,
                        float* __restrict__ out) {
    int b = blockIdx.x, t = threadIdx.x;  // 64 threads
    __shared__ float qs[128];
    __shared__ float w2s[2];
    qs[t] = g_qstar[b * 128 + t];
    qs[64 + t] = g_qstar[b * 128 + 64 + t];
    __syncthreads();
    float acc = b1[t];
    #pragma unroll 8
    for (int k = 0; k < 128; k++) acc += qs[k] * W1[k * 64 + t];
    acc = fmaxf(acc, 0.f);
    float z = acc * W2[t];
    #pragma unroll
    for (int off = 16; off; off >>= 1) z += __shfl_down_sync(0xffffffffu, z, off);
    if ((t & 31) == 0) w2s[t >> 5] = z;
    __syncthreads();
    if (t == 0) out[b] = w2s[0] + w2s[1] + b2[0];
}

// ---------------- orchestration ----------------
extern "C" void kernel_launch(void* const* d_in, const int* in_sizes, int n_in,
                              void* d_out, int out_size) {
    const float* x   = (const float*)d_in[0];
    const void*  ei  = d_in[1];
    const void*  bt  = d_in[2];
    const float* W0  = (const float*)d_in[3];
    const float* b0  = (const float*)d_in[4];
    const float* Wg  = (const float*)d_in[5];
    const float* asr = (const float*)d_in[6];
    const float* ads = (const float*)d_in[7];
    const float* bg  = (const float*)d_in[8];
    const float* Wh  = (const float*)d_in[9];
    const float* bh  = (const float*)d_in[10];
    const float* Wih = (const float*)d_in[11];
    const float* Whh = (const float*)d_in[12];
    const float* bih = (const float*)d_in[13];
    const float* bhh = (const float*)d_in[14];
    const float* W1  = (const float*)d_in[15];
    const float* b1  = (const float*)d_in[16];
    const float* W2  = (const float*)d_in[17];
    const float* b2  = (const float*)d_in[18];
    float* out = (float*)d_out;

    k_detect<<<1, 256>>>((const int*)ei, (const int*)bt);
    k_lin0<<<(N_NODES * DIM + 255) / 256, 256>>>(x, W0, b0);

    k_deg_init<<<(N_NODES + 256) / 256 + 1, 256>>>();
    k_hist<<<(E_EDGES + 255) / 256, 256>>>(ei);
    k_scan<<<1, 1024>>>();
    k_pos<<<(N_NODES + 255) / 256, 256>>>();
    k_scatter<<<(E_EDGES + N_NODES + 255) / 256, 256>>>(ei);

    k_gemm_xh<<<dim3(8, (N_NODES + 63) / 64), 256>>>(Wg, asr, ads);
    k_agg<<<N_NODES, 128>>>(bg);
    k_gemm_out<<<(N_NODES + 63) / 64, 256>>>(Wh, bh);

    k_boff<<<1, 256>>>(bt);
    k_zero_s2s<<<(B_BATCH * 2 * DIM + 255) / 256, 256>>>();
    for (int step = 0; step < 3; step++) {
        k_lstm<<<B_BATCH, 256>>>(Wih, Whh, bih, bhh);
        k_s2s_att<<<B_BATCH, 256>>>();
    }
    k_final<<<B_BATCH, 64>>>(W1, b1, W2, b2, out);
}

// round 3
// speedup vs baseline: 1.0242x; 1.0242x over previous
#include <cuda_runtime.h>
#include <cuda_bf16.h>
#include <math.h>

#define N_NODES 20000
#define E_EDGES 320000
#define B_BATCH 128
#define IN_F    25
#define DIM     64
#define H_HEADS 8
#define ETOT    (E_EDGES + N_NODES)

#define NEG_INF (__int_as_float(0xff800000))

// ---------------- scratch (device globals; no runtime allocation) ----------------
__device__ float g_h0[N_NODES * DIM];
__device__ __nv_bfloat16 g_xh[(size_t)N_NODES * H_HEADS * DIM];   // bf16: 20.5 MB
__device__ float g_as[N_NODES * H_HEADS];
__device__ float g_ad[N_NODES * H_HEADS];
__device__ int   g_off[N_NODES + 1];
__device__ int   g_pos[N_NODES];
__device__ int   g_esrc[ETOT];
__device__ float g_aggr[(size_t)N_NODES * H_HEADS * DIM];         // fp32: 41 MB
__device__ float g_out[N_NODES * DIM];
__device__ int   g_is64[2];   // [0]=edge_index is int64, [1]=batch is int64

// ---------------- dtype detection (int32 vs int64 arrays) ----------------
__global__ void k_detect(const int* ei32, const int* bt32) {
    int t = threadIdx.x;  // 256 threads
    int nz = (ei32[2 * t + 1] != 0) ? 1 : 0;
    int any_e = __syncthreads_or(nz);
    int nzb = (bt32[10000 + 2 * t + 1] != 0) ? 1 : 0;
    int any_b = __syncthreads_or(nzb);
    if (t == 0) { g_is64[0] = any_e ? 0 : 1; g_is64[1] = any_b ? 0 : 1; }
}

__device__ __forceinline__ int ld_idx(const void* p, long i, int is64) {
    return is64 ? (int)((const long long*)p)[i] : ((const int*)p)[i];
}

// ---------------- h0 = relu(x @ W0 + b0) ----------------
__global__ void k_lin0(const float* __restrict__ x, const float* __restrict__ W0,
                       const float* __restrict__ b0) {
    __shared__ float sW[IN_F * DIM];
    __shared__ float sb[DIM];
    int tid = threadIdx.x;
    for (int i = tid; i < IN_F * DIM; i += 256) sW[i] = W0[i];
    if (tid < DIM) sb[tid] = b0[tid];
    __syncthreads();
    int idx = blockIdx.x * 256 + tid;
    if (idx < N_NODES * DIM) {
        int n = idx >> 6, c = idx & 63;
        float acc = sb[c];
        const float* xr = &x[n * IN_F];
        #pragma unroll
        for (int k = 0; k < IN_F; k++) acc += xr[k] * sW[k * DIM + c];
        g_h0[idx] = fmaxf(acc, 0.f);
    }
}

// ---------------- xh = h0 @ Wg (bf16 out) + fused a_s/a_d per-head dots ----------------
// grid (8 heads, 157 row-tiles), 128 threads, BM=128 BN=64 K=64, micro 8x8
__global__ void k_gemm_xh(const float* __restrict__ Wg, const float* __restrict__ att_src,
                          const float* __restrict__ att_dst) {
    const int h  = blockIdx.x;
    const int m0 = blockIdx.y * 128;
    const int tid = threadIdx.x;
    const int tx = tid & 7, ty = tid >> 3;     // tx: 8 col-groups, ty: 16 row-groups
    __shared__ float Ast[64 * 128];            // [k][m], 32 KB
    __shared__ float Bs[64 * 64];              // [k][n], 16 KB

    // Load A: thread owns one row
    {
        int row = m0 + tid;
        if (row < N_NODES) {
            const float4* src = (const float4*)&g_h0[row * 64];
            #pragma unroll
            for (int q = 0; q < 16; q++) {
                float4 v = src[q];
                Ast[(4 * q + 0) * 128 + tid] = v.x;
                Ast[(4 * q + 1) * 128 + tid] = v.y;
                Ast[(4 * q + 2) * 128 + tid] = v.z;
                Ast[(4 * q + 3) * 128 + tid] = v.w;
            }
        } else {
            #pragma unroll
            for (int k = 0; k < 64; k++) Ast[k * 128 + tid] = 0.f;
        }
    }
    // Load B (head h column block of Wg [64][512])
    #pragma unroll
    for (int l = 0; l < 8; l++) {
        int lin4 = l * 128 + tid;
        int k = lin4 >> 4, n4 = lin4 & 15;
        float4 v = *(const float4*)&Wg[k * 512 + h * 64 + n4 * 4];
        *(float4*)&Bs[k * 64 + n4 * 4] = v;
    }
    __syncthreads();

    float acc[8][8] = {};
    #pragma unroll 8
    for (int k = 0; k < 64; k++) {
        float a[8], b[8];
        *(float4*)&a[0] = *(const float4*)&Ast[k * 128 + ty * 8];
        *(float4*)&a[4] = *(const float4*)&Ast[k * 128 + ty * 8 + 4];
        *(float4*)&b[0] = *(const float4*)&Bs[k * 64 + tx * 8];
        *(float4*)&b[4] = *(const float4*)&Bs[k * 64 + tx * 8 + 4];
        #pragma unroll
        for (int i = 0; i < 8; i++)
            #pragma unroll
            for (int j = 0; j < 8; j++) acc[i][j] += a[i] * b[j];
    }

    float as8[8], ad8[8];
    #pragma unroll
    for (int j = 0; j < 8; j++) {
        as8[j] = att_src[h * 64 + tx * 8 + j];
        ad8[j] = att_dst[h * 64 + tx * 8 + j];
    }
    #pragma unroll
    for (int i = 0; i < 8; i++) {
        int row = m0 + ty * 8 + i;
        float ps = 0.f, pd = 0.f;
        if (row < N_NODES) {
            union { __nv_bfloat162 h2[4]; uint4 u; } pk;
            #pragma unroll
            for (int q = 0; q < 4; q++)
                pk.h2[q] = __floats2bfloat162_rn(acc[i][2 * q], acc[i][2 * q + 1]);
            *(uint4*)&g_xh[(size_t)row * 512 + h * 64 + tx * 8] = pk.u;
            #pragma unroll
            for (int j = 0; j < 8; j++) { ps += acc[i][j] * as8[j]; pd += acc[i][j] * ad8[j]; }
        }
        #pragma unroll
        for (int off = 4; off; off >>= 1) {
            ps += __shfl_down_sync(0xffffffffu, ps, off, 8);
            pd += __shfl_down_sync(0xffffffffu, pd, off, 8);
        }
        if (tx == 0 && row < N_NODES) {
            g_as[row * 8 + h] = ps;
            g_ad[row * 8 + h] = pd;
        }
    }
}

// ---------------- CSR build (by dst, incl. self-loops) ----------------
__global__ void k_hist(const void* ei) {
    int base = blockIdx.x * 1024 + threadIdx.x;
    int is64 = g_is64[0];
    #pragma unroll
    for (int u = 0; u < 4; u++) {
        int e = base + u * 256;
        if (e < E_EDGES) {
            int dst = ld_idx(ei, (long)E_EDGES + e, is64);
            atomicAdd(&g_off[dst + 1], 1);
        }
    }
}
// 1 block, 1024 threads: scan of (count + 1 self-loop) -> offsets, and g_pos copy
__global__ void k_scan() {
    __shared__ int partial[1024];
    const int total = N_NODES + 1;
    const int per = (total + 1023) / 1024;
    int t = threadIdx.x;
    int beg = t * per, end = min(beg + per, total);
    int s = 0;
    for (int i = beg; i < end; i++) s += g_off[i] + (i > 0 ? 1 : 0);
    partial[t] = s;
    __syncthreads();
    for (int d = 1; d < 1024; d <<= 1) {
        int v = (t >= d) ? partial[t - d] : 0;
        __syncthreads();
        partial[t] += v;
        __syncthreads();
    }
    int run = (t == 0) ? 0 : partial[t - 1];
    for (int i = beg; i < end; i++) {
        run += g_off[i] + (i > 0 ? 1 : 0);
        g_off[i] = run;
        if (i < N_NODES) g_pos[i] = run;
    }
}
__global__ void k_scatter(const void* ei) {
    int t = blockIdx.x * 256 + threadIdx.x;
    int is64 = g_is64[0];
    if (t < E_EDGES) {
        int src = ld_idx(ei, t, is64);
        int dst = ld_idx(ei, (long)E_EDGES + t, is64);
        int slot = atomicAdd(&g_pos[dst], 1);
        g_esrc[slot] = src;
    } else if (t < E_EDGES + N_NODES) {
        int n = t - E_EDGES;
        int slot = atomicAdd(&g_pos[n], 1);
        g_esrc[slot] = n;  // self-loop
    }
}

// ---------------- per-dst online softmax + aggregation (bf16 gather), fused relu(+bg) ----
// grid 20000 blocks, 64 threads: head = tid>>3, 8 channels per thread
__global__ void k_agg(const float* __restrict__ bg) {
    int nid = blockIdx.x;
    int tid = threadIdx.x;
    int h = tid >> 3, cg = tid & 7;
    float adh = g_ad[nid * 8 + h];
    int beg = g_off[nid], end = g_off[nid + 1];
    float m = NEG_INF, s = 0.f;
    float a[8] = {};
    const uint4* xh4 = (const uint4*)g_xh;   // 8 bf16 per uint4; 64 uint4 per row
    int lane_off = h * 8 + cg;
    for (int j = beg; j < end; j++) {
        int src = g_esrc[j];
        float e = g_as[src * 8 + h] + adh;
        e = (e > 0.f) ? e : 0.2f * e;        // leaky_relu 0.2
        float mn = fmaxf(m, e);
        float wo = __expf(m - mn);
        float we = __expf(e - mn);
        union { uint4 u; __nv_bfloat162 h2[4]; } cv;
        cv.u = xh4[(size_t)src * 64 + lane_off];
        s = s * wo + we;
        #pragma unroll
        for (int q = 0; q < 4; q++) {
            float2 f = __bfloat1622float2(cv.h2[q]);
            a[2 * q]     = a[2 * q]     * wo + we * f.x;
            a[2 * q + 1] = a[2 * q + 1] * wo + we * f.y;
        }
        m = mn;
    }
    float inv = 1.f / s;
    int c0 = h * 64 + cg * 8;
    float4 o0, o1;
    const float4 bg0 = *(const float4*)&bg[c0];
    const float4 bg1 = *(const float4*)&bg[c0 + 4];
    o0.x = fmaxf(a[0] * inv + bg0.x, 0.f);
    o0.y = fmaxf(a[1] * inv + bg0.y, 0.f);
    o0.z = fmaxf(a[2] * inv + bg0.z, 0.f);
    o0.w = fmaxf(a[3] * inv + bg0.w, 0.f);
    o1.x = fmaxf(a[4] * inv + bg1.x, 0.f);
    o1.y = fmaxf(a[5] * inv + bg1.y, 0.f);
    o1.z = fmaxf(a[6] * inv + bg1.z, 0.f);
    o1.w = fmaxf(a[7] * inv + bg1.w, 0.f);
    *(float4*)&g_aggr[(size_t)nid * 512 + c0] = o0;
    *(float4*)&g_aggr[(size_t)nid * 512 + c0 + 4] = o1;
}

// ---------------- out = relu(aggr @ Wh + bh)  M=20000 N=64 K=512 ----------------
// grid 313, 128 threads, BM=64 BN=64, micro 8x4
__global__ void k_gemm_out(const float* __restrict__ Wh, const float* __restrict__ bh) {
    const int m0 = blockIdx.x * 64;
    const int tid = threadIdx.x;
    const int tx = tid & 15, ty = tid >> 4;    // tx: 16 col-groups of 4, ty: 8 row-groups of 8
    __shared__ float Ast[64 * 64];             // [k][m], 16 KB
    __shared__ float Bs[64 * 64];              // [k][n], 16 KB
    float acc[8][4] = {};
    const int r = tid & 63, half = tid >> 6;   // A-load: 2 threads per row
    for (int kk = 0; kk < 512; kk += 64) {
        {
            int row = m0 + r;
            if (row < N_NODES) {
                const float4* src = (const float4*)&g_aggr[(size_t)row * 512 + kk];
                #pragma unroll
                for (int q = 0; q < 8; q++) {
                    float4 v = src[half * 8 + q];
                    int k = (half * 8 + q) * 4;
                    Ast[(k + 0) * 64 + r] = v.x;
                    Ast[(k + 1) * 64 + r] = v.y;
                    Ast[(k + 2) * 64 + r] = v.z;
                    Ast[(k + 3) * 64 + r] = v.w;
                }
            } else {
                #pragma unroll
                for (int q = 0; q < 32; q++) Ast[(half * 32 + q) * 64 + r] = 0.f;
            }
        }
        #pragma unroll
        for (int l = 0; l < 8; l++) {
            int lin4 = l * 128 + tid;
            int k = lin4 >> 4, n4 = lin4 & 15;
            float4 v = *(const float4*)&Wh[(kk + k) * 64 + n4 * 4];
            *(float4*)&Bs[k * 64 + n4 * 4] = v;
        }
        __syncthreads();
        #pragma unroll 8
        for (int k = 0; k < 64; k++) {
            float a[8], b[4];
            *(float4*)&a[0] = *(const float4*)&Ast[k * 64 + ty * 8];
            *(float4*)&a[4] = *(const float4*)&Ast[k * 64 + ty * 8 + 4];
            *(float4*)&b[0] = *(const float4*)&Bs[k * 64 + tx * 4];
            #pragma unroll
            for (int i = 0; i < 8; i++)
                #pragma unroll
                for (int j = 0; j < 4; j++) acc[i][j] += a[i] * b[j];
        }
        __syncthreads();
    }
    float bh4[4];
    #pragma unroll
    for (int j = 0; j < 4; j++) bh4[j] = bh[tx * 4 + j];
    #pragma unroll
    for (int i = 0; i < 8; i++) {
        int row = m0 + ty * 8 + i;
        if (row < N_NODES) {
            float4 o;
            o.x = fmaxf(acc[i][0] + bh4[0], 0.f);
            o.y = fmaxf(acc[i][1] + bh4[1], 0.f);
            o.z = fmaxf(acc[i][2] + bh4[2], 0.f);
            o.w = fmaxf(acc[i][3] + bh4[3], 0.f);
            *(float4*)&g_out[row * 64 + tx * 4] = o;
        }
    }
}

__device__ __forceinline__ float sigmoidf_(float x) { return 1.f / (1.f + __expf(-x)); }

// ---------------- fully fused Set2Set (3 steps LSTM+attention) + final MLP ----------------
// 128 blocks (one per graph), 256 threads. Everything per-graph is independent.
__global__ void k_s2s(const void* bt,
                      const float* __restrict__ W_ih, const float* __restrict__ W_hh,
                      const float* __restrict__ b_ih, const float* __restrict__ b_hh,
                      const float* __restrict__ W1, const float* __restrict__ b1,
                      const float* __restrict__ W2, const float* __restrict__ b2,
                      float* __restrict__ out) {
    int b = blockIdx.x, tid = threadIdx.x;
    __shared__ float sq[128], sh[64], sc[64], gsh[256];
    __shared__ float wred[8], gm[4], gs[4], gr[4][64];
    __shared__ int sbnd[2];
    if (tid < 2) {
        int target = b + tid;
        int is64 = g_is64[1];
        int lo = 0, hi = N_NODES;
        while (lo < hi) {
            int mid = (lo + hi) >> 1;
            int v = ld_idx(bt, mid, is64);
            if (v < target) lo = mid + 1; else hi = mid;
        }
        sbnd[tid] = lo;
    }
    if (tid < 128) sq[tid] = 0.f;
    if (tid < 64) { sh[tid] = 0.f; sc[tid] = 0.f; }
    __syncthreads();
    int beg = sbnd[0], end = sbnd[1];
    int cnt = end - beg;
    int iters = (cnt + 3) >> 2;
    int grp = tid >> 6, c = tid & 63;

    for (int step = 0; step < 3; step++) {
        // ---- LSTM cell: gate tid of 256 ----
        float acc = b_ih[tid] + b_hh[tid];
        const float* wi = &W_ih[tid * 128];
        #pragma unroll 4
        for (int k = 0; k < 128; k++) acc += sq[k] * wi[k];
        const float* wh = &W_hh[tid * 64];
        #pragma unroll 4
        for (int k = 0; k < 64; k++) acc += sh[k] * wh[k];
        gsh[tid] = acc;
        __syncthreads();
        if (tid < 64) {
            float ig = sigmoidf_(gsh[tid]);
            float fg = sigmoidf_(gsh[64 + tid]);
            float gg = tanhf(gsh[128 + tid]);
            float og = sigmoidf_(gsh[192 + tid]);
            float cv = fg * sc[tid] + ig * gg;
            sc[tid] = cv;
            sh[tid] = og * tanhf(cv);
        }
        __syncthreads();
        // ---- attention with q = sh, online softmax over this graph's nodes ----
        float m = NEG_INF, s = 0.f, racc = 0.f;
        for (int it = 0; it < iters; it++) {
            int i = beg + it * 4 + grp;
            bool valid = (i < end);
            float v = valid ? g_out[(size_t)i * 64 + c] : 0.f;
            float p = v * sh[c];
            #pragma unroll
            for (int off = 16; off; off >>= 1) p += __shfl_down_sync(0xffffffffu, p, off);
            if ((tid & 31) == 0) wred[tid >> 5] = p;
            __syncthreads();
            float e = wred[grp * 2] + wred[grp * 2 + 1];
            __syncthreads();
            if (valid) {
                float mn = fmaxf(m, e);
                float wo = __expf(m - mn);
                float we = __expf(e - mn);
                s = s * wo + we;
                racc = racc * wo + we * v;
                m = mn;
            }
        }
        if (c == 0) { gm[grp] = m; gs[grp] = s; }
        gr[grp][c] = racc;
        __syncthreads();
        if (tid < 64) {
            float M = NEG_INF;
            #pragma unroll
            for (int g = 0; g < 4; g++) M = fmaxf(M, gm[g]);
            float S = 0.f, R = 0.f;
            #pragma unroll
            for (int g = 0; g < 4; g++) {
                float w = (gm[g] == NEG_INF) ? 0.f : __expf(gm[g] - M);
                S += gs[g] * w;
                R += gr[g][tid] * w;
            }
            float r = (S > 0.f) ? (R / S) : 0.f;
            sq[tid] = sh[tid];
            sq[64 + tid] = r;
        }
        __syncthreads();
    }
    // ---- final MLP: y = relu(q_star@W1+b1)@W2+b2 ----
    if (tid < 64) {
        float acc = b1[tid];
        #pragma unroll 4
        for (int k = 0; k < 128; k++) acc += sq[k] * W1[k * 64 + tid];
        acc = fmaxf(acc, 0.f);
        float z = acc * W2[tid];
        #pragma unroll
        for (int off = 16; off; off >>= 1) z += __shfl_down_sync(0xffffffffu, z, off);
        if ((tid & 31) == 0) wred[tid >> 5] = z;
    }
    __syncthreads();
    if (tid == 0) out[b] = wred[0] + wred[1] + b2[0];
}

// ---------------- orchestration ----------------
extern "C" void kernel_launch(void* const* d_in, const int* in_sizes, int n_in,
                              void* d_out, int out_size) {
    const float* x   = (const float*)d_in[0];
    const void*  ei  = d_in[1];
    const void*  bt  = d_in[2];
    const float* W0  = (const float*)d_in[3];
    const float* b0  = (const float*)d_in[4];
    const float* Wg  = (const float*)d_in[5];
    const float* asr = (const float*)d_in[6];
    const float* ads = (const float*)d_in[7];
    const float* bg  = (const float*)d_in[8];
    const float* Wh  = (const float*)d_in[9];
    const float* bh  = (const float*)d_in[10];
    const float* Wih = (const float*)d_in[11];
    const float* Whh = (const float*)d_in[12];
    const float* bih = (const float*)d_in[13];
    const float* bhh = (const float*)d_in[14];
    const float* W1  = (const float*)d_in[15];
    const float* b1  = (const float*)d_in[16];
    const float* W2  = (const float*)d_in[17];
    const float* b2  = (const float*)d_in[18];
    float* out = (float*)d_out;

    void* off_ptr = nullptr;
    cudaGetSymbolAddress(&off_ptr, g_off);

    k_detect<<<1, 256>>>((const int*)ei, (const int*)bt);
    cudaMemsetAsync(off_ptr, 0, (N_NODES + 1) * sizeof(int));
    k_lin0<<<(N_NODES * DIM + 255) / 256, 256>>>(x, W0, b0);
    k_hist<<<(E_EDGES + 1023) / 1024, 256>>>(ei);
    k_scan<<<1, 1024>>>();
    k_scatter<<<(E_EDGES + N_NODES + 255) / 256, 256>>>(ei);

    k_gemm_xh<<<dim3(8, (N_NODES + 127) / 128), 128>>>(Wg, asr, ads);
    k_agg<<<N_NODES, 64>>>(bg);
    k_gemm_out<<<(N_NODES + 63) / 64, 128>>>(Wh, bh);

    k_s2s<<<B_BATCH, 256>>>(bt, Wih, Whh, bih, bhh, W1, b1, W2, b2, out);
}

// round 6
// speedup vs baseline: 1.1689x; 1.1413x over previous
#include <cuda_runtime.h>
#include <cuda_bf16.h>
#include <stdint.h>
#include <math.h>

#define N_NODES 20000
#define E_EDGES 320000
#define B_BATCH 128
#define IN_F    25
#define DIM     64
#define H_HEADS 8
#define ETOT    (E_EDGES + N_NODES)
#define SCAN_BLKS 20

#define NEG_INF (__int_as_float(0xff800000))

// ---------------- scratch (device globals; no runtime allocation) ----------------
__device__ float g_h0[N_NODES * DIM];
__device__ __nv_bfloat16 g_xh[(size_t)N_NODES * H_HEADS * DIM];   // bf16: 20.5 MB
__device__ float g_as[N_NODES * H_HEADS];
__device__ float g_ad[N_NODES * H_HEADS];
__device__ int   g_off[N_NODES + 1];
__device__ int   g_pos[N_NODES];
__device__ int   g_esrc[ETOT];
__device__ float g_aggr[(size_t)N_NODES * H_HEADS * DIM];         // fp32: 41 MB
__device__ float g_out[N_NODES * DIM];
__device__ int   g_is64[2];
__device__ int   g_chainv[SCAN_BLKS + 1];
__device__ int   g_chainf[SCAN_BLKS + 1];

__device__ __forceinline__ unsigned int f2tf32(float f) {
    unsigned int u;
    asm("cvt.rna.tf32.f32 %0, %1;" : "=r"(u) : "f"(f));
    return u;
}

__device__ __forceinline__ void mma_tf32(float c[4], const unsigned int a[4],
                                         const unsigned int b[2]) {
    asm volatile(
        "mma.sync.aligned.m16n8k8.row.col.f32.tf32.tf32.f32 "
        "{%0,%1,%2,%3}, {%4,%5,%6,%7}, {%8,%9}, {%0,%1,%2,%3};"
        : "+f"(c[0]), "+f"(c[1]), "+f"(c[2]), "+f"(c[3])
        : "r"(a[0]), "r"(a[1]), "r"(a[2]), "r"(a[3]), "r"(b[0]), "r"(b[1]));
}

// ---------------- dtype detection (int32 vs int64 arrays) ----------------
__global__ void k_detect(const int* ei32, const int* bt32) {
    int t = threadIdx.x;  // 256 threads
    int nz = (ei32[2 * t + 1] != 0) ? 1 : 0;
    int any_e = __syncthreads_or(nz);
    int nzb = (bt32[10000 + 2 * t + 1] != 0) ? 1 : 0;
    int any_b = __syncthreads_or(nzb);
    if (t == 0) { g_is64[0] = any_e ? 0 : 1; g_is64[1] = any_b ? 0 : 1; }
}

__device__ __forceinline__ int ld_idx(const void* p, long i, int is64) {
    return is64 ? (int)((const long long*)p)[i] : ((const int*)p)[i];
}

// ---------------- h0 = relu(x @ W0 + b0) ----------------
__global__ void k_lin0(const float* __restrict__ x, const float* __restrict__ W0,
                       const float* __restrict__ b0) {
    __shared__ float sW[IN_F * DIM];
    __shared__ float sb[DIM];
    int tid = threadIdx.x;
    for (int i = tid; i < IN_F * DIM; i += 256) sW[i] = W0[i];
    if (tid < DIM) sb[tid] = b0[tid];
    __syncthreads();
    int idx = blockIdx.x * 256 + tid;
    if (idx < N_NODES * DIM) {
        int n = idx >> 6, c = idx & 63;
        float acc = sb[c];
        const float* xr = &x[n * IN_F];
        #pragma unroll
        for (int k = 0; k < IN_F; k++) acc += xr[k] * sW[k * DIM + c];
        g_h0[idx] = fmaxf(acc, 0.f);
    }
}

// ---------------- xh = h0 @ Wg (tf32 mma, bf16 out) + fused a_s/a_d dots ----------------
// grid (8 heads, 157 row-tiles), 256 threads (8 warps, 4x2 warp grid), BM=128 BN=64
#define LDA 33
#define LDB 66
#define LDC 66
__global__ void k_gemm_xh(const float* __restrict__ Wg, const float* __restrict__ att_src,
                          const float* __restrict__ att_dst) {
    const int h  = blockIdx.x;
    const int m0 = blockIdx.y * 128;
    const int tid = threadIdx.x;
    __shared__ unsigned int pool[128 * LDC];      // As (128*33) | Bs (64*66); Cs overlays all
    unsigned int* As = pool;
    unsigned int* Bs = pool + 128 * LDA;
    float* Cs = (float*)pool;
    __shared__ float sAs[64], sAd[64];

    if (tid < 64) sAs[tid] = att_src[h * 64 + tid];
    else if (tid < 128) sAd[tid - 64] = att_dst[h * 64 + tid - 64];

    // Load B once: Wg[k*512 + h*64 + n], 64x64 -> Bs[k*LDB + n]
    #pragma unroll
    for (int l = 0; l < 4; l++) {
        int lin4 = l * 256 + tid;
        int k = lin4 >> 4, n4 = lin4 & 15;
        float4 v = *(const float4*)&Wg[k * 512 + h * 64 + n4 * 4];
        Bs[k * LDB + n4 * 4 + 0] = f2tf32(v.x);
        Bs[k * LDB + n4 * 4 + 1] = f2tf32(v.y);
        Bs[k * LDB + n4 * 4 + 2] = f2tf32(v.z);
        Bs[k * LDB + n4 * 4 + 3] = f2tf32(v.w);
    }

    const int wid = tid >> 5, lane = tid & 31;
    const int wm = wid >> 1, wn = wid & 1;
    const int mW = wm * 32, nW = wn * 32;
    const int g = lane >> 2, tg = lane & 3;

    float c[2][4][4] = {};

    #pragma unroll
    for (int kk = 0; kk < 64; kk += 32) {
        // load A chunk: rows 128 x 32 k (relative), tf32
        {
            int r = tid >> 1, half = tid & 1;
            int row = m0 + r;
            int ks = half * 16;
            if (row < N_NODES) {
                #pragma unroll
                for (int q = 0; q < 4; q++) {
                    float4 v = *(const float4*)&g_h0[row * 64 + kk + ks + q * 4];
                    As[r * LDA + ks + q * 4 + 0] = f2tf32(v.x);
                    As[r * LDA + ks + q * 4 + 1] = f2tf32(v.y);
                    As[r * LDA + ks + q * 4 + 2] = f2tf32(v.z);
                    As[r * LDA + ks + q * 4 + 3] = f2tf32(v.w);
                }
            } else {
                #pragma unroll
                for (int q = 0; q < 16; q++) As[r * LDA + ks + q] = 0u;
            }
        }
        __syncthreads();
        #pragma unroll
        for (int kq = 0; kq < 4; kq++) {
            int k0 = kq * 8;
            unsigned int a[2][4], b[4][2];
            #pragma unroll
            for (int mi = 0; mi < 2; mi++) {
                int r0 = mW + mi * 16 + g;
                a[mi][0] = As[(r0)     * LDA + k0 + tg];
                a[mi][1] = As[(r0 + 8) * LDA + k0 + tg];
                a[mi][2] = As[(r0)     * LDA + k0 + tg + 4];
                a[mi][3] = As[(r0 + 8) * LDA + k0 + tg + 4];
            }
            #pragma unroll
            for (int ni = 0; ni < 4; ni++) {
                int cn = nW + ni * 8 + g;
                b[ni][0] = Bs[(kk + k0 + tg)     * LDB + cn];
                b[ni][1] = Bs[(kk + k0 + tg + 4) * LDB + cn];
            }
            #pragma unroll
            for (int mi = 0; mi < 2; mi++)
                #pragma unroll
                for (int ni = 0; ni < 4; ni++) mma_tf32(c[mi][ni], a[mi], b[ni]);
        }
        __syncthreads();
    }

    // store C tile to smem (overlays As/Bs)
    #pragma unroll
    for (int mi = 0; mi < 2; mi++) {
        int rA = mW + mi * 16 + g;
        #pragma unroll
        for (int ni = 0; ni < 4; ni++) {
            int c0 = nW + ni * 8 + tg * 2;
            *(float2*)&Cs[(rA)     * LDC + c0] = make_float2(c[mi][ni][0], c[mi][ni][1]);
            *(float2*)&Cs[(rA + 8) * LDC + c0] = make_float2(c[mi][ni][2], c[mi][ni][3]);
        }
    }
    __syncthreads();

    // epilogue: 2 threads per row; bf16 pack + per-head att dots
    {
        int r = tid >> 1, half = tid & 1;
        int row = m0 + r;
        int cb = half * 32;
        float ps = 0.f, pd = 0.f;
        if (row < N_NODES) {
            #pragma unroll
            for (int q = 0; q < 4; q++) {       // 4 x uint4 (8 bf16 each)
                union { __nv_bfloat162 h2[4]; uint4 u; } pk;
                #pragma unroll
                for (int e = 0; e < 4; e++) {
                    float v0 = Cs[r * LDC + cb + q * 8 + 2 * e];
                    float v1 = Cs[r * LDC + cb + q * 8 + 2 * e + 1];
                    pk.h2[e] = __floats2bfloat162_rn(v0, v1);
                    ps += v0 * sAs[cb + q * 8 + 2 * e] + v1 * sAs[cb + q * 8 + 2 * e + 1];
                    pd += v0 * sAd[cb + q * 8 + 2 * e] + v1 * sAd[cb + q * 8 + 2 * e + 1];
                }
                *(uint4*)&g_xh[(size_t)row * 512 + h * 64 + cb + q * 8] = pk.u;
            }
        }
        ps += __shfl_xor_sync(0xffffffffu, ps, 1);
        pd += __shfl_xor_sync(0xffffffffu, pd, 1);
        if (half == 0 && row < N_NODES) {
            g_as[row * 8 + h] = ps;
            g_ad[row * 8 + h] = pd;
        }
    }
}

// ---------------- CSR build (by dst, incl. self-loops) ----------------
__global__ void k_hist(const void* ei) {
    int base = blockIdx.x * 1024 + threadIdx.x;
    int is64 = g_is64[0];
    #pragma unroll
    for (int u = 0; u < 4; u++) {
        int e = base + u * 256;
        if (e < E_EDGES) {
            int dst = ld_idx(ei, (long)E_EDGES + e, is64);
            atomicAdd(&g_off[dst + 1], 1);
        }
    }
}

// chained multi-block exclusive scan of (deg + 1), one launch, 20 blocks x 1024
__global__ void k_scan() {
    int b = blockIdx.x, t = threadIdx.x;
    int i = b * 1024 + t;
    int v = (i < N_NODES) ? (g_off[i + 1] + 1) : 0;
    int lane = t & 31, w = t >> 5;
    int x = v;
    #pragma unroll
    for (int d = 1; d < 32; d <<= 1) {
        int y = __shfl_up_sync(0xffffffffu, x, d);
        if (lane >= d) x += y;
    }
    __shared__ int wsum[32];
    __shared__ int sbase;
    if (lane == 31) wsum[w] = x;
    __syncthreads();
    if (w == 0) {
        int y = wsum[lane];
        #pragma unroll
        for (int d = 1; d < 32; d <<= 1) {
            int z = __shfl_up_sync(0xffffffffu, y, d);
            if (lane >= d) y += z;
        }
        wsum[lane] = y;
    }
    __syncthreads();
    int incl = x + (w > 0 ? wsum[w - 1] : 0);
    if (t == 0) {
        int base = 0;
        if (b > 0) {
            while (((volatile int*)g_chainf)[b] == 0) {}
            __threadfence();
            base = ((volatile int*)g_chainv)[b];
        }
        ((volatile int*)g_chainv)[b + 1] = base + wsum[31];
        __threadfence();
        ((volatile int*)g_chainf)[b + 1] = 1;
        sbase = base;
    }
    __syncthreads();
    if (i < N_NODES) {
        int off = sbase + incl;
        g_off[i + 1] = off;
        g_pos[i] = off - v;
    }
}

__global__ void k_scatter(const void* ei) {
    int t = blockIdx.x * 256 + threadIdx.x;
    int is64 = g_is64[0];
    if (t < E_EDGES) {
        int src = ld_idx(ei, t, is64);
        int dst = ld_idx(ei, (long)E_EDGES + t, is64);
        int slot = atomicAdd(&g_pos[dst], 1);
        g_esrc[slot] = src;
    } else if (t < E_EDGES + N_NODES) {
        int n = t - E_EDGES;
        int slot = atomicAdd(&g_pos[n], 1);
        g_esrc[slot] = n;  // self-loop
    }
}

// ---------------- per-dst online softmax + aggregation (bf16 gather) ----------------
// grid 20000 blocks, 64 threads: head = tid>>3, 8 channels per thread; prefetched
__global__ void k_agg(const float* __restrict__ bg) {
    int nid = blockIdx.x;
    int tid = threadIdx.x;
    int h = tid >> 3, cg = tid & 7;
    float adh = g_ad[nid * 8 + h];
    int beg = g_off[nid], end = g_off[nid + 1];
    float m = NEG_INF, s = 0.f;
    float a[8] = {};
    const uint4* xh4 = (const uint4*)g_xh;
    int lane_off = h * 8 + cg;

    int src = g_esrc[beg];
    float asv = g_as[src * 8 + h];
    uint4 cvu = xh4[(size_t)src * 64 + lane_off];
    for (int j = beg; j < end; j++) {
        float asn = 0.f; uint4 cvn = make_uint4(0, 0, 0, 0);
        if (j + 1 < end) {
            int srcn = g_esrc[j + 1];
            asn = g_as[srcn * 8 + h];
            cvn = xh4[(size_t)srcn * 64 + lane_off];
        }
        float e = asv + adh;
        e = (e > 0.f) ? e : 0.2f * e;
        float mn = fmaxf(m, e);
        float wo = __expf(m - mn);
        float we = __expf(e - mn);
        union { uint4 u; __nv_bfloat162 h2[4]; } cv;
        cv.u = cvu;
        s = s * wo + we;
        #pragma unroll
        for (int q = 0; q < 4; q++) {
            float2 f = __bfloat1622float2(cv.h2[q]);
            a[2 * q]     = a[2 * q]     * wo + we * f.x;
            a[2 * q + 1] = a[2 * q + 1] * wo + we * f.y;
        }
        m = mn;
        asv = asn; cvu = cvn;
    }
    float inv = 1.f / s;
    int c0 = h * 64 + cg * 8;
    float4 o0, o1;
    const float4 bg0 = *(const float4*)&bg[c0];
    const float4 bg1 = *(const float4*)&bg[c0 + 4];
    o0.x = fmaxf(a[0] * inv + bg0.x, 0.f);
    o0.y = fmaxf(a[1] * inv + bg0.y, 0.f);
    o0.z = fmaxf(a[2] * inv + bg0.z, 0.f);
    o0.w = fmaxf(a[3] * inv + bg0.w, 0.f);
    o1.x = fmaxf(a[4] * inv + bg1.x, 0.f);
    o1.y = fmaxf(a[5] * inv + bg1.y, 0.f);
    o1.z = fmaxf(a[6] * inv + bg1.z, 0.f);
    o1.w = fmaxf(a[7] * inv + bg1.w, 0.f);
    *(float4*)&g_aggr[(size_t)nid * 512 + c0] = o0;
    *(float4*)&g_aggr[(size_t)nid * 512 + c0 + 4] = o1;
}

// ---------------- out = relu(aggr @ Wh + bh), tf32 mma. M=20000 N=64 K=512 ----------------
// grid 313 (BM=64), 128 threads (4 warps, 2x2 warp grid)
#define LDA2 65
__global__ void k_gemm_out(const float* __restrict__ Wh, const float* __restrict__ bh) {
    const int m0 = blockIdx.x * 64;
    const int tid = threadIdx.x;
    __shared__ unsigned int As[64 * LDA2];
    __shared__ unsigned int Bs[64 * LDB];
    const int wid = tid >> 5, lane = tid & 31;
    const int mW = (wid >> 1) * 32, nW = (wid & 1) * 32;
    const int g = lane >> 2, tg = lane & 3;
    float c[2][4][4] = {};

    for (int kk = 0; kk < 512; kk += 64) {
        {   // load A 64x64 chunk
            int r = tid >> 1, half = tid & 1;
            int row = m0 + r;
            int ks = half * 32;
            if (row < N_NODES) {
                #pragma unroll
                for (int q = 0; q < 8; q++) {
                    float4 v = *(const float4*)&g_aggr[(size_t)row * 512 + kk + ks + q * 4];
                    As[r * LDA2 + ks + q * 4 + 0] = f2tf32(v.x);
                    As[r * LDA2 + ks + q * 4 + 1] = f2tf32(v.y);
                    As[r * LDA2 + ks + q * 4 + 2] = f2tf32(v.z);
                    As[r * LDA2 + ks + q * 4 + 3] = f2tf32(v.w);
                }
            } else {
                #pragma unroll
                for (int q = 0; q < 32; q++) As[r * LDA2 + ks + q] = 0u;
            }
        }
        #pragma unroll
        for (int l = 0; l < 8; l++) {   // load B 64x64 chunk
            int lin4 = l * 128 + tid;
            int k = lin4 >> 4, n4 = lin4 & 15;
            float4 v = *(const float4*)&Wh[(kk + k) * 64 + n4 * 4];
            Bs[k * LDB + n4 * 4 + 0] = f2tf32(v.x);
            Bs[k * LDB + n4 * 4 + 1] = f2tf32(v.y);
            Bs[k * LDB + n4 * 4 + 2] = f2tf32(v.z);
            Bs[k * LDB + n4 * 4 + 3] = f2tf32(v.w);
        }
        __syncthreads();
        #pragma unroll
        for (int kq = 0; kq < 8; kq++) {
            int k0 = kq * 8;
            unsigned int a[2][4], b[4][2];
            #pragma unroll
            for (int mi = 0; mi < 2; mi++) {
                int r0 = mW + mi * 16 + g;
                a[mi][0] = As[(r0)     * LDA2 + k0 + tg];
                a[mi][1] = As[(r0 + 8) * LDA2 + k0 + tg];
                a[mi][2] = As[(r0)     * LDA2 + k0 + tg + 4];
                a[mi][3] = As[(r0 + 8) * LDA2 + k0 + tg + 4];
            }
            #pragma unroll
            for (int ni = 0; ni < 4; ni++) {
                int cn = nW + ni * 8 + g;
                b[ni][0] = Bs[(k0 + tg)     * LDB + cn];
                b[ni][1] = Bs[(k0 + tg + 4) * LDB + cn];
            }
            #pragma unroll
            for (int mi = 0; mi < 2; mi++)
                #pragma unroll
                for (int ni = 0; ni < 4; ni++) mma_tf32(c[mi][ni], a[mi], b[ni]);
        }
        __syncthreads();
    }

    float2 bh2[4];
    #pragma unroll
    for (int ni = 0; ni < 4; ni++) bh2[ni] = *(const float2*)&bh[nW + ni * 8 + tg * 2];
    #pragma unroll
    for (int mi = 0; mi < 2; mi++) {
        int rA = m0 + mW + mi * 16 + g;
        #pragma unroll
        for (int ni = 0; ni < 4; ni++) {
            int col = nW + ni * 8 + tg * 2;
            if (rA < N_NODES) {
                float2 o = make_float2(fmaxf(c[mi][ni][0] + bh2[ni].x, 0.f),
                                       fmaxf(c[mi][ni][1] + bh2[ni].y, 0.f));
                *(float2*)&g_out[rA * 64 + col] = o;
            }
            if (rA + 8 < N_NODES) {
                float2 o = make_float2(fmaxf(c[mi][ni][2] + bh2[ni].x, 0.f),
                                       fmaxf(c[mi][ni][3] + bh2[ni].y, 0.f));
                *(float2*)&g_out[(rA + 8) * 64 + col] = o;
            }
        }
    }
}

__device__ __forceinline__ float sigmoidf_(float x) { return 1.f / (1.f + __expf(-x)); }

// ---------------- fused Set2Set (3 steps) + final MLP; warp-per-node attention --------
__global__ void k_s2s(const void* bt,
                      const float* __restrict__ W_ih, const float* __restrict__ W_hh,
                      const float* __restrict__ b_ih, const float* __restrict__ b_hh,
                      const float* __restrict__ W1, const float* __restrict__ b1,
                      const float* __restrict__ W2, const float* __restrict__ b2,
                      float* __restrict__ out) {
    int b = blockIdx.x, tid = threadIdx.x;
    int warp = tid >> 5, lane = tid & 31;
    __shared__ float sq[128], sh[64], sc[64], gsh[256];
    __shared__ float wm_[8], ws_[8], wr_[8][64];
    __shared__ float fin[2];
    __shared__ int sbnd[2];
    if (tid < 2) {
        int target = b + tid;
        int is64 = g_is64[1];
        int lo = 0, hi = N_NODES;
        while (lo < hi) {
            int mid = (lo + hi) >> 1;
            int v = ld_idx(bt, mid, is64);
            if (v < target) lo = mid + 1; else hi = mid;
        }
        sbnd[tid] = lo;
    }
    if (tid < 128) sq[tid] = 0.f;
    if (tid < 64) { sh[tid] = 0.f; sc[tid] = 0.f; }
    __syncthreads();
    int beg = sbnd[0], end = sbnd[1];

    for (int step = 0; step < 3; step++) {
        // ---- LSTM cell ----
        float acc = b_ih[tid] + b_hh[tid];
        const float* wi = &W_ih[tid * 128];
        #pragma unroll 4
        for (int k = 0; k < 128; k++) acc += sq[k] * wi[k];
        const float* wh = &W_hh[tid * 64];
        #pragma unroll 4
        for (int k = 0; k < 64; k++) acc += sh[k] * wh[k];
        gsh[tid] = acc;
        __syncthreads();
        if (tid < 64) {
            float ig = sigmoidf_(gsh[tid]);
            float fg = sigmoidf_(gsh[64 + tid]);
            float gg = tanhf(gsh[128 + tid]);
            float og = sigmoidf_(gsh[192 + tid]);
            float cv = fg * sc[tid] + ig * gg;
            sc[tid] = cv;
            sh[tid] = og * tanhf(cv);
        }
        __syncthreads();
        // ---- attention, warp-per-node, no block sync in loop ----
        float2 q2 = *(const float2*)&sh[2 * lane];
        float m = NEG_INF, s = 0.f;
        float2 r2 = make_float2(0.f, 0.f);
        int i = beg + warp;
        float2 v = (i < end) ? *(const float2*)&g_out[(size_t)i * 64 + 2 * lane]
                             : make_float2(0.f, 0.f);
        for (; i < end; i += 8) {
            int inext = i + 8;
            float2 vn = (inext < end) ? *(const float2*)&g_out[(size_t)inext * 64 + 2 * lane]
                                      : make_float2(0.f, 0.f);
            float p = v.x * q2.x + v.y * q2.y;
            #pragma unroll
            for (int off = 16; off; off >>= 1) p += __shfl_xor_sync(0xffffffffu, p, off);
            float mn = fmaxf(m, p);
            float wo = __expf(m - mn);
            float we = __expf(p - mn);
            s = s * wo + we;
            r2.x = r2.x * wo + we * v.x;
            r2.y = r2.y * wo + we * v.y;
            m = mn;
            v = vn;
        }
        if (lane == 0) { wm_[warp] = m; ws_[warp] = s; }
        wr_[warp][2 * lane] = r2.x;
        wr_[warp][2 * lane + 1] = r2.y;
        __syncthreads();
        if (tid < 64) {
            float M = NEG_INF;
            #pragma unroll
            for (int w = 0; w < 8; w++) M = fmaxf(M, wm_[w]);
            float S = 0.f, R = 0.f;
            #pragma unroll
            for (int w = 0; w < 8; w++) {
                float f = (wm_[w] == NEG_INF) ? 0.f : __expf(wm_[w] - M);
                S += ws_[w] * f;
                R += wr_[w][tid] * f;
            }
            float r = (S > 0.f) ? (R / S) : 0.f;
            sq[tid] = sh[tid];
            sq[64 + tid] = r;
        }
        __syncthreads();
    }
    // ---- final MLP ----
    if (tid < 64) {
        float acc = b1[tid];
        #pragma unroll 4
        for (int k = 0; k < 128; k++) acc += sq[k] * W1[k * 64 + tid];
        acc = fmaxf(acc, 0.f);
        float z = acc * W2[tid];
        #pragma unroll
        for (int off = 16; off; off >>= 1) z += __shfl_down_sync(0xffffffffu, z, off);
        if ((tid & 31) == 0) fin[tid >> 5] = z;
    }
    __syncthreads();
    if (tid == 0) out[b] = fin[0] + fin[1] + b2[0];
}

// ---------------- orchestration ----------------
extern "C" void kernel_launch(void* const* d_in, const int* in_sizes, int n_in,
                              void* d_out, int out_size) {
    const float* x   = (const float*)d_in[0];
    const void*  ei  = d_in[1];
    const void*  bt  = d_in[2];
    const float* W0  = (const float*)d_in[3];
    const float* b0  = (const float*)d_in[4];
    const float* Wg  = (const float*)d_in[5];
    const float* asr = (const float*)d_in[6];
    const float* ads = (const float*)d_in[7];
    const float* bg  = (const float*)d_in[8];
    const float* Wh  = (const float*)d_in[9];
    const float* bh  = (const float*)d_in[10];
    const float* Wih = (const float*)d_in[11];
    const float* Whh = (const float*)d_in[12];
    const float* bih = (const float*)d_in[13];
    const float* bhh = (const float*)d_in[14];
    const float* W1  = (const float*)d_in[15];
    const float* b1  = (const float*)d_in[16];
    const float* W2  = (const float*)d_in[17];
    const float* b2  = (const float*)d_in[18];
    float* out = (float*)d_out;

    void* off_ptr = nullptr;
    void* flg_ptr = nullptr;
    cudaGetSymbolAddress(&off_ptr, g_off);
    cudaGetSymbolAddress(&flg_ptr, g_chainf);

    k_detect<<<1, 256>>>((const int*)ei, (const int*)bt);
    cudaMemsetAsync(off_ptr, 0, (N_NODES + 1) * sizeof(int));
    cudaMemsetAsync(flg_ptr, 0, (SCAN_BLKS + 1) * sizeof(int));
    k_lin0<<<(N_NODES * DIM + 255) / 256, 256>>>(x, W0, b0);
    k_hist<<<(E_EDGES + 1023) / 1024, 256>>>(ei);
    k_scan<<<SCAN_BLKS, 1024>>>();
    k_scatter<<<(E_EDGES + N_NODES + 255) / 256, 256>>>(ei);

    k_gemm_xh<<<dim3(8, (N_NODES + 127) / 128), 256>>>(Wg, asr, ads);
    k_agg<<<N_NODES, 64>>>(bg);
    k_gemm_out<<<(N_NODES + 63) / 64, 128>>>(Wh, bh);

    k_s2s<<<B_BATCH, 256>>>(bt, Wih, Whh, bih, bhh, W1, b1, W2, b2, out);
}

// round 7
// speedup vs baseline: 1.4519x; 1.2422x over previous
#include <cuda_runtime.h>
#include <cuda_bf16.h>
#include <stdint.h>
#include <math.h>

#define N_NODES 20000
#define E_EDGES 320000
#define B_BATCH 128
#define IN_F    25
#define DIM     64
#define H_HEADS 8
#define ETOT    (E_EDGES + N_NODES)
#define SCAN_BLKS 20

#define NEG_INF (__int_as_float(0xff800000))

// ---------------- scratch (device globals; no runtime allocation) ----------------
__device__ float g_h0[N_NODES * DIM];
__device__ __nv_bfloat16 g_xh[(size_t)N_NODES * H_HEADS * DIM];    // bf16: 20.5 MB
__device__ float g_as[N_NODES * H_HEADS];
__device__ float g_ad[N_NODES * H_HEADS];
__device__ int   g_off[N_NODES + 1];
__device__ int   g_pos[N_NODES];
__device__ int   g_esrc[ETOT];
__device__ __nv_bfloat16 g_aggrh[(size_t)N_NODES * H_HEADS * DIM]; // bf16: 20.5 MB
__device__ float g_out[N_NODES * DIM];
__device__ int   g_is64[2];
__device__ int   g_chainv[SCAN_BLKS];

__device__ __forceinline__ unsigned int f2tf32(float f) {
    unsigned int u;
    asm("cvt.rna.tf32.f32 %0, %1;" : "=r"(u) : "f"(f));
    return u;
}

__device__ __forceinline__ void mma_tf32(float c[4], const unsigned int a[4],
                                         const unsigned int b[2]) {
    asm volatile(
        "mma.sync.aligned.m16n8k8.row.col.f32.tf32.tf32.f32 "
        "{%0,%1,%2,%3}, {%4,%5,%6,%7}, {%8,%9}, {%0,%1,%2,%3};"
        : "+f"(c[0]), "+f"(c[1]), "+f"(c[2]), "+f"(c[3])
        : "r"(a[0]), "r"(a[1]), "r"(a[2]), "r"(a[3]), "r"(b[0]), "r"(b[1]));
}

__device__ __forceinline__ void mma_bf16(float c[4], const unsigned int a[4],
                                         const unsigned int b[2]) {
    asm volatile(
        "mma.sync.aligned.m16n8k16.row.col.f32.bf16.bf16.f32 "
        "{%0,%1,%2,%3}, {%4,%5,%6,%7}, {%8,%9}, {%0,%1,%2,%3};"
        : "+f"(c[0]), "+f"(c[1]), "+f"(c[2]), "+f"(c[3])
        : "r"(a[0]), "r"(a[1]), "r"(a[2]), "r"(a[3]), "r"(b[0]), "r"(b[1]));
}

// ---------------- dtype detection (int32 vs int64 arrays) ----------------
__global__ void k_detect(const int* ei32, const int* bt32) {
    int t = threadIdx.x;  // 256 threads
    int nz = (ei32[2 * t + 1] != 0) ? 1 : 0;
    int any_e = __syncthreads_or(nz);
    int nzb = (bt32[10000 + 2 * t + 1] != 0) ? 1 : 0;
    int any_b = __syncthreads_or(nzb);
    if (t == 0) { g_is64[0] = any_e ? 0 : 1; g_is64[1] = any_b ? 0 : 1; }
}

__device__ __forceinline__ int ld_idx(const void* p, long i, int is64) {
    return is64 ? (int)((const long long*)p)[i] : ((const int*)p)[i];
}

// ---------------- h0 = relu(x @ W0 + b0) ----------------
__global__ void k_lin0(const float* __restrict__ x, const float* __restrict__ W0,
                       const float* __restrict__ b0) {
    __shared__ float sW[IN_F * DIM];
    __shared__ float sb[DIM];
    int tid = threadIdx.x;
    for (int i = tid; i < IN_F * DIM; i += 256) sW[i] = W0[i];
    if (tid < DIM) sb[tid] = b0[tid];
    __syncthreads();
    int idx = blockIdx.x * 256 + tid;
    if (idx < N_NODES * DIM) {
        int n = idx >> 6, c = idx & 63;
        float acc = sb[c];
        const float* xr = &x[n * IN_F];
        #pragma unroll
        for (int k = 0; k < IN_F; k++) acc += xr[k] * sW[k * DIM + c];
        g_h0[idx] = fmaxf(acc, 0.f);
    }
}

// ---------------- xh = h0 @ Wg (tf32 mma, bf16 out) + fused a_s/a_d dots ----------------
// grid (8 heads, 157 row-tiles), 256 threads (8 warps, 4x2 warp grid), BM=128 BN=64
#define LDA 33
#define LDB 66
#define LDC 66
__global__ void k_gemm_xh(const float* __restrict__ Wg, const float* __restrict__ att_src,
                          const float* __restrict__ att_dst) {
    const int h  = blockIdx.x;
    const int m0 = blockIdx.y * 128;
    const int tid = threadIdx.x;
    __shared__ unsigned int pool[128 * LDC];      // As (128*33) | Bs (64*66); Cs overlays all
    unsigned int* As = pool;
    unsigned int* Bs = pool + 128 * LDA;
    float* Cs = (float*)pool;
    __shared__ float sAs[64], sAd[64];

    if (tid < 64) sAs[tid] = att_src[h * 64 + tid];
    else if (tid < 128) sAd[tid - 64] = att_dst[h * 64 + tid - 64];

    // Load B once: Wg[k*512 + h*64 + n], 64x64 -> Bs[k*LDB + n]
    #pragma unroll
    for (int l = 0; l < 4; l++) {
        int lin4 = l * 256 + tid;
        int k = lin4 >> 4, n4 = lin4 & 15;
        float4 v = *(const float4*)&Wg[k * 512 + h * 64 + n4 * 4];
        Bs[k * LDB + n4 * 4 + 0] = f2tf32(v.x);
        Bs[k * LDB + n4 * 4 + 1] = f2tf32(v.y);
        Bs[k * LDB + n4 * 4 + 2] = f2tf32(v.z);
        Bs[k * LDB + n4 * 4 + 3] = f2tf32(v.w);
    }

    const int wid = tid >> 5, lane = tid & 31;
    const int wm = wid >> 1, wn = wid & 1;
    const int mW = wm * 32, nW = wn * 32;
    const int g = lane >> 2, tg = lane & 3;

    float c[2][4][4] = {};

    #pragma unroll
    for (int kk = 0; kk < 64; kk += 32) {
        // load A chunk: rows 128 x 32 k (relative), tf32
        {
            int r = tid >> 1, half = tid & 1;
            int row = m0 + r;
            int ks = half * 16;
            if (row < N_NODES) {
                #pragma unroll
                for (int q = 0; q < 4; q++) {
                    float4 v = *(const float4*)&g_h0[row * 64 + kk + ks + q * 4];
                    As[r * LDA + ks + q * 4 + 0] = f2tf32(v.x);
                    As[r * LDA + ks + q * 4 + 1] = f2tf32(v.y);
                    As[r * LDA + ks + q * 4 + 2] = f2tf32(v.z);
                    As[r * LDA + ks + q * 4 + 3] = f2tf32(v.w);
                }
            } else {
                #pragma unroll
                for (int q = 0; q < 16; q++) As[r * LDA + ks + q] = 0u;
            }
        }
        __syncthreads();
        #pragma unroll
        for (int kq = 0; kq < 4; kq++) {
            int k0 = kq * 8;
            unsigned int a[2][4], b[4][2];
            #pragma unroll
            for (int mi = 0; mi < 2; mi++) {
                int r0 = mW + mi * 16 + g;
                a[mi][0] = As[(r0)     * LDA + k0 + tg];
                a[mi][1] = As[(r0 + 8) * LDA + k0 + tg];
                a[mi][2] = As[(r0)     * LDA + k0 + tg + 4];
                a[mi][3] = As[(r0 + 8) * LDA + k0 + tg + 4];
            }
            #pragma unroll
            for (int ni = 0; ni < 4; ni++) {
                int cn = nW + ni * 8 + g;
                b[ni][0] = Bs[(kk + k0 + tg)     * LDB + cn];
                b[ni][1] = Bs[(kk + k0 + tg + 4) * LDB + cn];
            }
            #pragma unroll
            for (int mi = 0; mi < 2; mi++)
                #pragma unroll
                for (int ni = 0; ni < 4; ni++) mma_tf32(c[mi][ni], a[mi], b[ni]);
        }
        __syncthreads();
    }

    // store C tile to smem (overlays As/Bs)
    #pragma unroll
    for (int mi = 0; mi < 2; mi++) {
        int rA = mW + mi * 16 + g;
        #pragma unroll
        for (int ni = 0; ni < 4; ni++) {
            int c0 = nW + ni * 8 + tg * 2;
            *(float2*)&Cs[(rA)     * LDC + c0] = make_float2(c[mi][ni][0], c[mi][ni][1]);
            *(float2*)&Cs[(rA + 8) * LDC + c0] = make_float2(c[mi][ni][2], c[mi][ni][3]);
        }
    }
    __syncthreads();

    // epilogue: 2 threads per row; bf16 pack + per-head att dots
    {
        int r = tid >> 1, half = tid & 1;
        int row = m0 + r;
        int cb = half * 32;
        float ps = 0.f, pd = 0.f;
        if (row < N_NODES) {
            #pragma unroll
            for (int q = 0; q < 4; q++) {       // 4 x uint4 (8 bf16 each)
                union { __nv_bfloat162 h2[4]; uint4 u; } pk;
                #pragma unroll
                for (int e = 0; e < 4; e++) {
                    float v0 = Cs[r * LDC + cb + q * 8 + 2 * e];
                    float v1 = Cs[r * LDC + cb + q * 8 + 2 * e + 1];
                    pk.h2[e] = __floats2bfloat162_rn(v0, v1);
                    ps += v0 * sAs[cb + q * 8 + 2 * e] + v1 * sAs[cb + q * 8 + 2 * e + 1];
                    pd += v0 * sAd[cb + q * 8 + 2 * e] + v1 * sAd[cb + q * 8 + 2 * e + 1];
                }
                *(uint4*)&g_xh[(size_t)row * 512 + h * 64 + cb + q * 8] = pk.u;
            }
        }
        ps += __shfl_xor_sync(0xffffffffu, ps, 1);
        pd += __shfl_xor_sync(0xffffffffu, pd, 1);
        if (half == 0 && row < N_NODES) {
            g_as[row * 8 + h] = ps;
            g_ad[row * 8 + h] = pd;
        }
    }
}

// ---------------- CSR build (by dst, incl. self-loops) ----------------
__global__ void k_hist(const void* ei) {
    int base = blockIdx.x * 1024 + threadIdx.x;
    int is64 = g_is64[0];
    #pragma unroll
    for (int u = 0; u < 4; u++) {
        int e = base + u * 256;
        if (e < E_EDGES) {
            int dst = ld_idx(ei, (long)E_EDGES + e, is64);
            atomicAdd(&g_off[dst + 1], 1);
        }
    }
}

// Phase A: per-block local inclusive scan of (deg + 1); block totals to g_chainv.
// Stashes deg in g_pos[i] for phase C.
__global__ void k_scanA() {
    int b = blockIdx.x, t = threadIdx.x;
    int i = b * 1024 + t;
    int v = (i < N_NODES) ? (g_off[i + 1] + 1) : 0;
    int lane = t & 31, w = t >> 5;
    int x = v;
    #pragma unroll
    for (int d = 1; d < 32; d <<= 1) {
        int y = __shfl_up_sync(0xffffffffu, x, d);
        if (lane >= d) x += y;
    }
    __shared__ int wsum[32];
    if (lane == 31) wsum[w] = x;
    __syncthreads();
    if (w == 0) {
        int y = wsum[lane];
        #pragma unroll
        for (int d = 1; d < 32; d <<= 1) {
            int z = __shfl_up_sync(0xffffffffu, y, d);
            if (lane >= d) y += z;
        }
        wsum[lane] = y;
    }
    __syncthreads();
    int incl = x + (w > 0 ? wsum[w - 1] : 0);
    if (t == 1023) g_chainv[b] = incl;
    if (i < N_NODES) {
        g_off[i + 1] = incl;   // block-local inclusive, base added in phase C
        g_pos[i] = v;          // stash deg+1
    }
}

// Phase B: one warp turns block totals into exclusive bases.
__global__ void k_scanB() {
    int t = threadIdx.x;  // 32
    int v = (t < SCAN_BLKS) ? g_chainv[t] : 0;
    int x = v;
    #pragma unroll
    for (int d = 1; d < 32; d <<= 1) {
        int y = __shfl_up_sync(0xffffffffu, x, d);
        if (t >= d) x += y;
    }
    if (t < SCAN_BLKS) g_chainv[t] = x - v;  // exclusive base
}

// Phase C: add base, finalize g_off (inclusive) and g_pos (exclusive start).
__global__ void k_scanC() {
    int b = blockIdx.x, t = threadIdx.x;
    int i = b * 1024 + t;
    if (i < N_NODES) {
        int base = g_chainv[b];
        int f = g_off[i + 1] + base;
        g_off[i + 1] = f;
        g_pos[i] = f - g_pos[i];
    }
}

__global__ void k_scatter(const void* ei) {
    int t = blockIdx.x * 256 + threadIdx.x;
    int is64 = g_is64[0];
    if (t < E_EDGES) {
        int src = ld_idx(ei, t, is64);
        int dst = ld_idx(ei, (long)E_EDGES + t, is64);
        int slot = atomicAdd(&g_pos[dst], 1);
        g_esrc[slot] = src;
    } else if (t < E_EDGES + N_NODES) {
        int n = t - E_EDGES;
        int slot = atomicAdd(&g_pos[n], 1);
        g_esrc[slot] = n;  // self-loop
    }
}

// ---------------- per-dst online softmax + aggregation (bf16 gather, bf16 out) --------
// grid 20000 blocks, 64 threads: head = tid>>3, 8 channels per thread; prefetched
__global__ void k_agg(const float* __restrict__ bg) {
    int nid = blockIdx.x;
    int tid = threadIdx.x;
    int h = tid >> 3, cg = tid & 7;
    float adh = g_ad[nid * 8 + h];
    int beg = g_off[nid], end = g_off[nid + 1];
    float m = NEG_INF, s = 0.f;
    float a[8] = {};
    const uint4* xh4 = (const uint4*)g_xh;
    int lane_off = h * 8 + cg;

    int src = g_esrc[beg];
    float asv = g_as[src * 8 + h];
    uint4 cvu = xh4[(size_t)src * 64 + lane_off];
    for (int j = beg; j < end; j++) {
        float asn = 0.f; uint4 cvn = make_uint4(0, 0, 0, 0);
        if (j + 1 < end) {
            int srcn = g_esrc[j + 1];
            asn = g_as[srcn * 8 + h];
            cvn = xh4[(size_t)srcn * 64 + lane_off];
        }
        float e = asv + adh;
        e = (e > 0.f) ? e : 0.2f * e;
        float mn = fmaxf(m, e);
        float wo = __expf(m - mn);
        float we = __expf(e - mn);
        union { uint4 u; __nv_bfloat162 h2[4]; } cv;
        cv.u = cvu;
        s = s * wo + we;
        #pragma unroll
        for (int q = 0; q < 4; q++) {
            float2 f = __bfloat1622float2(cv.h2[q]);
            a[2 * q]     = a[2 * q]     * wo + we * f.x;
            a[2 * q + 1] = a[2 * q + 1] * wo + we * f.y;
        }
        m = mn;
        asv = asn; cvu = cvn;
    }
    float inv = 1.f / s;
    int c0 = h * 64 + cg * 8;
    const float4 bg0 = *(const float4*)&bg[c0];
    const float4 bg1 = *(const float4*)&bg[c0 + 4];
    union { __nv_bfloat162 h2[4]; uint4 u; } pk;
    pk.h2[0] = __floats2bfloat162_rn(fmaxf(a[0] * inv + bg0.x, 0.f),
                                     fmaxf(a[1] * inv + bg0.y, 0.f));
    pk.h2[1] = __floats2bfloat162_rn(fmaxf(a[2] * inv + bg0.z, 0.f),
                                     fmaxf(a[3] * inv + bg0.w, 0.f));
    pk.h2[2] = __floats2bfloat162_rn(fmaxf(a[4] * inv + bg1.x, 0.f),
                                     fmaxf(a[5] * inv + bg1.y, 0.f));
    pk.h2[3] = __floats2bfloat162_rn(fmaxf(a[6] * inv + bg1.z, 0.f),
                                     fmaxf(a[7] * inv + bg1.w, 0.f));
    *(uint4*)&g_aggrh[(size_t)nid * 512 + c0] = pk.u;
}

// ---------------- out = relu(aggr @ Wh + bh), bf16 mma m16n8k16. M=20000 N=64 K=512 ----
// grid 313 (BM=64), 128 threads (4 warps, 2x2 warp grid)
#define LDAP 33   // A pairs stride (32 pairs + pad)
#define LDBP 65   // B pairs stride along k: Bs32[kp*LDBP + n]
__global__ void k_gemm_out(const float* __restrict__ Wh, const float* __restrict__ bh) {
    const int m0 = blockIdx.x * 64;
    const int tid = threadIdx.x;
    __shared__ unsigned int As32[64 * LDAP];   // 64 rows x 32 bf16-pairs
    __shared__ unsigned int Bs32[32 * LDBP];   // 32 k-pairs x 64 cols
    const int wid = tid >> 5, lane = tid & 31;
    const int mW = (wid >> 1) * 32, nW = (wid & 1) * 32;
    const int g = lane >> 2, tg = lane & 3;
    float c[2][4][4] = {};

    for (int kk = 0; kk < 512; kk += 64) {
        {   // load A 64x64 bf16 chunk (already paired in memory)
            int r = tid >> 1, half = tid & 1;
            int row = m0 + r;
            if (row < N_NODES) {
                const uint4* src = (const uint4*)&g_aggrh[(size_t)row * 512 + kk + half * 32];
                #pragma unroll
                for (int q = 0; q < 4; q++) {
                    uint4 v = src[q];
                    int p = half * 16 + q * 4;
                    As32[r * LDAP + p + 0] = v.x;
                    As32[r * LDAP + p + 1] = v.y;
                    As32[r * LDAP + p + 2] = v.z;
                    As32[r * LDAP + p + 3] = v.w;
                }
            } else {
                #pragma unroll
                for (int q = 0; q < 16; q++) As32[r * LDAP + half * 16 + q] = 0u;
            }
        }
        #pragma unroll
        for (int l = 0; l < 16; l++) {   // load B 64x64 chunk as k-pairs
            int lin = l * 128 + tid;
            int kp = lin >> 6, n = lin & 63;
            float w0 = Wh[(kk + 2 * kp) * 64 + n];
            float w1 = Wh[(kk + 2 * kp + 1) * 64 + n];
            __nv_bfloat162 p2 = __floats2bfloat162_rn(w0, w1);
            Bs32[kp * LDBP + n] = *(unsigned int*)&p2;
        }
        __syncthreads();
        #pragma unroll
        for (int kq = 0; kq < 4; kq++) {    // 16 k per iter
            int kp0 = kq * 8;
            unsigned int a[2][4], b[4][2];
            #pragma unroll
            for (int mi = 0; mi < 2; mi++) {
                int r0 = mW + mi * 16 + g;
                a[mi][0] = As32[(r0)     * LDAP + kp0 + tg];
                a[mi][1] = As32[(r0 + 8) * LDAP + kp0 + tg];
                a[mi][2] = As32[(r0)     * LDAP + kp0 + tg + 4];
                a[mi][3] = As32[(r0 + 8) * LDAP + kp0 + tg + 4];
            }
            #pragma unroll
            for (int ni = 0; ni < 4; ni++) {
                int cn = nW + ni * 8 + g;
                b[ni][0] = Bs32[(kp0 + tg)     * LDBP + cn];
                b[ni][1] = Bs32[(kp0 + tg + 4) * LDBP + cn];
            }
            #pragma unroll
            for (int mi = 0; mi < 2; mi++)
                #pragma unroll
                for (int ni = 0; ni < 4; ni++) mma_bf16(c[mi][ni], a[mi], b[ni]);
        }
        __syncthreads();
    }

    float2 bh2[4];
    #pragma unroll
    for (int ni = 0; ni < 4; ni++) bh2[ni] = *(const float2*)&bh[nW + ni * 8 + tg * 2];
    #pragma unroll
    for (int mi = 0; mi < 2; mi++) {
        int rA = m0 + mW + mi * 16 + g;
        #pragma unroll
        for (int ni = 0; ni < 4; ni++) {
            int col = nW + ni * 8 + tg * 2;
            if (rA < N_NODES) {
                float2 o = make_float2(fmaxf(c[mi][ni][0] + bh2[ni].x, 0.f),
                                       fmaxf(c[mi][ni][1] + bh2[ni].y, 0.f));
                *(float2*)&g_out[rA * 64 + col] = o;
            }
            if (rA + 8 < N_NODES) {
                float2 o = make_float2(fmaxf(c[mi][ni][2] + bh2[ni].x, 0.f),
                                       fmaxf(c[mi][ni][3] + bh2[ni].y, 0.f));
                *(float2*)&g_out[(rA + 8) * 64 + col] = o;
            }
        }
    }
}

__device__ __forceinline__ float sigmoidf_(float x) { return 1.f / (1.f + __expf(-x)); }

// ---------------- fused Set2Set (3 steps) + final MLP; warp-per-node attention --------
__global__ void k_s2s(const void* bt,
                      const float* __restrict__ W_ih, const float* __restrict__ W_hh,
                      const float* __restrict__ b_ih, const float* __restrict__ b_hh,
                      const float* __restrict__ W1, const float* __restrict__ b1,
                      const float* __restrict__ W2, const float* __restrict__ b2,
                      float* __restrict__ out) {
    int b = blockIdx.x, tid = threadIdx.x;
    int warp = tid >> 5, lane = tid & 31;
    __shared__ float sq[128], sh[64], sc[64], gsh[256];
    __shared__ float wm_[8], ws_[8], wr_[8][64];
    __shared__ float fin[2];
    __shared__ int sbnd[2];
    if (tid < 2) {
        int target = b + tid;
        int is64 = g_is64[1];
        int lo = 0, hi = N_NODES;
        while (lo < hi) {
            int mid = (lo + hi) >> 1;
            int v = ld_idx(bt, mid, is64);
            if (v < target) lo = mid + 1; else hi = mid;
        }
        sbnd[tid] = lo;
    }
    if (tid < 128) sq[tid] = 0.f;
    if (tid < 64) { sh[tid] = 0.f; sc[tid] = 0.f; }
    __syncthreads();
    int beg = sbnd[0], end = sbnd[1];

    for (int step = 0; step < 3; step++) {
        // ---- LSTM cell ----
        float acc = b_ih[tid] + b_hh[tid];
        const float* wi = &W_ih[tid * 128];
        #pragma unroll 4
        for (int k = 0; k < 128; k++) acc += sq[k] * wi[k];
        const float* wh = &W_hh[tid * 64];
        #pragma unroll 4
        for (int k = 0; k < 64; k++) acc += sh[k] * wh[k];
        gsh[tid] = acc;
        __syncthreads();
        if (tid < 64) {
            float ig = sigmoidf_(gsh[tid]);
            float fg = sigmoidf_(gsh[64 + tid]);
            float gg = tanhf(gsh[128 + tid]);
            float og = sigmoidf_(gsh[192 + tid]);
            float cv = fg * sc[tid] + ig * gg;
            sc[tid] = cv;
            sh[tid] = og * tanhf(cv);
        }
        __syncthreads();
        // ---- attention, warp-per-node, no block sync in loop ----
        float2 q2 = *(const float2*)&sh[2 * lane];
        float m = NEG_INF, s = 0.f;
        float2 r2 = make_float2(0.f, 0.f);
        int i = beg + warp;
        float2 v = (i < end) ? *(const float2*)&g_out[(size_t)i * 64 + 2 * lane]
                             : make_float2(0.f, 0.f);
        for (; i < end; i += 8) {
            int inext = i + 8;
            float2 vn = (inext < end) ? *(const float2*)&g_out[(size_t)inext * 64 + 2 * lane]
                                      : make_float2(0.f, 0.f);
            float p = v.x * q2.x + v.y * q2.y;
            #pragma unroll
            for (int off = 16; off; off >>= 1) p += __shfl_xor_sync(0xffffffffu, p, off);
            float mn = fmaxf(m, p);
            float wo = __expf(m - mn);
            float we = __expf(p - mn);
            s = s * wo + we;
            r2.x = r2.x * wo + we * v.x;
            r2.y = r2.y * wo + we * v.y;
            m = mn;
            v = vn;
        }
        if (lane == 0) { wm_[warp] = m; ws_[warp] = s; }
        wr_[warp][2 * lane] = r2.x;
        wr_[warp][2 * lane + 1] = r2.y;
        __syncthreads();
        if (tid < 64) {
            float M = NEG_INF;
            #pragma unroll
            for (int w = 0; w < 8; w++) M = fmaxf(M, wm_[w]);
            float S = 0.f, R = 0.f;
            #pragma unroll
            for (int w = 0; w < 8; w++) {
                float f = (wm_[w] == NEG_INF) ? 0.f : __expf(wm_[w] - M);
                S += ws_[w] * f;
                R += wr_[w][tid] * f;
            }
            float r = (S > 0.f) ? (R / S) : 0.f;
            sq[tid] = sh[tid];
            sq[64 + tid] = r;
        }
        __syncthreads();
    }
    // ---- final MLP ----
    if (tid < 64) {
        float acc = b1[tid];
        #pragma unroll 4
        for (int k = 0; k < 128; k++) acc += sq[k] * W1[k * 64 + tid];
        acc = fmaxf(acc, 0.f);
        float z = acc * W2[tid];
        #pragma unroll
        for (int off = 16; off; off >>= 1) z += __shfl_down_sync(0xffffffffu, z, off);
        if ((tid & 31) == 0) fin[tid >> 5] = z;
    }
    __syncthreads();
    if (tid == 0) out[b] = fin[0] + fin[1] + b2[0];
}

// ---------------- orchestration ----------------
extern "C" void kernel_launch(void* const* d_in, const int* in_sizes, int n_in,
                              void* d_out, int out_size) {
    const float* x   = (const float*)d_in[0];
    const void*  ei  = d_in[1];
    const void*  bt  = d_in[2];
    const float* W0  = (const float*)d_in[3];
    const float* b0  = (const float*)d_in[4];
    const float* Wg  = (const float*)d_in[5];
    const float* asr = (const float*)d_in[6];
    const float* ads = (const float*)d_in[7];
    const float* bg  = (const float*)d_in[8];
    const float* Wh  = (const float*)d_in[9];
    const float* bh  = (const float*)d_in[10];
    const float* Wih = (const float*)d_in[11];
    const float* Whh = (const float*)d_in[12];
    const float* bih = (const float*)d_in[13];
    const float* bhh = (const float*)d_in[14];
    const float* W1  = (const float*)d_in[15];
    const float* b1  = (const float*)d_in[16];
    const float* W2  = (const float*)d_in[17];
    const float* b2  = (const float*)d_in[18];
    float* out = (float*)d_out;

    void* off_ptr = nullptr;
    cudaGetSymbolAddress(&off_ptr, g_off);

    k_detect<<<1, 256>>>((const int*)ei, (const int*)bt);
    cudaMemsetAsync(off_ptr, 0, (N_NODES + 1) * sizeof(int));
    k_lin0<<<(N_NODES * DIM + 255) / 256, 256>>>(x, W0, b0);
    k_hist<<<(E_EDGES + 1023) / 1024, 256>>>(ei);
    k_scanA<<<SCAN_BLKS, 1024>>>();
    k_scanB<<<1, 32>>>();
    k_scanC<<<SCAN_BLKS, 1024>>>();
    k_scatter<<<(E_EDGES + N_NODES + 255) / 256, 256>>>(ei);

    k_gemm_xh<<<dim3(8, (N_NODES + 127) / 128), 256>>>(Wg, asr, ads);
    k_agg<<<N_NODES, 64>>>(bg);
    k_gemm_out<<<(N_NODES + 63) / 64, 128>>>(Wh, bh);

    k_s2s<<<B_BATCH, 256>>>(bt, Wih, Whh, bih, bhh, W1, b1, W2, b2, out);
}

// round 8
// speedup vs baseline: 1.6086x; 1.1079x over previous
#include <cuda_runtime.h>
#include <cuda_bf16.h>
#include <stdint.h>
#include <math.h>

#define N_NODES 20000
#define E_EDGES 320000
#define B_BATCH 128
#define IN_F    25
#define DIM     64
#define H_HEADS 8
#define ETOT    (E_EDGES + N_NODES)
#define SCAN_BLKS 20

#define NEG_INF (__int_as_float(0xff800000))

// ---------------- scratch (device globals; no runtime allocation) ----------------
__device__ unsigned int g_h0h[N_NODES * 32];                       // bf16x2 packed h0
__device__ __nv_bfloat16 g_xh[(size_t)N_NODES * H_HEADS * DIM];    // bf16: 20.5 MB
__device__ float g_as[N_NODES * H_HEADS];
__device__ float g_ad[N_NODES * H_HEADS];
__device__ int   g_off[N_NODES + 1];
__device__ int   g_pos[N_NODES];
__device__ int   g_esrc[ETOT];
__device__ __nv_bfloat16 g_aggrh[(size_t)N_NODES * H_HEADS * DIM]; // bf16: 20.5 MB
__device__ float g_out[N_NODES * DIM];
__device__ int   g_is64[2];
__device__ int   g_chainv[SCAN_BLKS];

__device__ __forceinline__ void mma_bf16(float c[4], const unsigned int a[4],
                                         const unsigned int b[2]) {
    asm volatile(
        "mma.sync.aligned.m16n8k16.row.col.f32.bf16.bf16.f32 "
        "{%0,%1,%2,%3}, {%4,%5,%6,%7}, {%8,%9}, {%0,%1,%2,%3};"
        : "+f"(c[0]), "+f"(c[1]), "+f"(c[2]), "+f"(c[3])
        : "r"(a[0]), "r"(a[1]), "r"(a[2]), "r"(a[3]), "r"(b[0]), "r"(b[1]));
}

// ---------------- dtype detection (int32 vs int64 arrays) ----------------
__global__ void k_detect(const int* ei32, const int* bt32) {
    int t = threadIdx.x;  // 256 threads
    int nz = (ei32[2 * t + 1] != 0) ? 1 : 0;
    int any_e = __syncthreads_or(nz);
    int nzb = (bt32[10000 + 2 * t + 1] != 0) ? 1 : 0;
    int any_b = __syncthreads_or(nzb);
    if (t == 0) { g_is64[0] = any_e ? 0 : 1; g_is64[1] = any_b ? 0 : 1; }
}

__device__ __forceinline__ int ld_idx(const void* p, long i, int is64) {
    return is64 ? (int)((const long long*)p)[i] : ((const int*)p)[i];
}

// ---------------- h0 = relu(x @ W0 + b0), packed bf16 output ----------------
__global__ void k_lin0(const float* __restrict__ x, const float* __restrict__ W0,
                       const float* __restrict__ b0) {
    __shared__ float sW[IN_F * DIM];
    __shared__ float sb[DIM];
    int tid = threadIdx.x;
    for (int i = tid; i < IN_F * DIM; i += 256) sW[i] = W0[i];
    if (tid < DIM) sb[tid] = b0[tid];
    __syncthreads();
    int idx = blockIdx.x * 256 + tid;  // over N*32 pairs
    if (idx < N_NODES * 32) {
        int n = idx >> 5, p = idx & 31;
        int c0 = 2 * p;
        float a0 = sb[c0], a1 = sb[c0 + 1];
        const float* xr = &x[n * IN_F];
        #pragma unroll
        for (int k = 0; k < IN_F; k++) {
            float xv = xr[k];
            a0 += xv * sW[k * DIM + c0];
            a1 += xv * sW[k * DIM + c0 + 1];
        }
        __nv_bfloat162 h2 = __floats2bfloat162_rn(fmaxf(a0, 0.f), fmaxf(a1, 0.f));
        g_h0h[n * 32 + p] = *(unsigned int*)&h2;
    }
}

// ---------------- xh = h0 @ Wg (bf16 mma, bf16 out) + fused a_s/a_d dots ----------------
// grid (8 heads, 157 row-tiles), 256 threads (8 warps, 4x2 warp grid), BM=128 BN=64 K=64
#define LDAP 33   // A bf16-pair stride (32 pairs + pad)
#define LDBP 65   // B pair stride along k
#define LDC  66
__global__ void k_gemm_xh(const float* __restrict__ Wg, const float* __restrict__ att_src,
                          const float* __restrict__ att_dst) {
    const int h  = blockIdx.x;
    const int m0 = blockIdx.y * 128;
    const int tid = threadIdx.x;
    __shared__ unsigned int pool[128 * LDC];      // As32 | Bs32 ; Cs overlays all
    unsigned int* As32 = pool;                    // 128 * 33
    unsigned int* Bs32 = pool + 128 * LDAP;       // 32 * 65
    float* Cs = (float*)pool;
    __shared__ float sAs[64], sAd[64];

    if (tid < 64) sAs[tid] = att_src[h * 64 + tid];
    else if (tid < 128) sAd[tid - 64] = att_dst[h * 64 + tid - 64];

    // Load B: Wg fp32 [64][512] head block -> bf16 k-pairs Bs32[kp*LDBP + n]
    #pragma unroll
    for (int l = 0; l < 8; l++) {
        int lin = l * 256 + tid;
        int kp = lin >> 6, n = lin & 63;
        float w0 = Wg[(2 * kp) * 512 + h * 64 + n];
        float w1 = Wg[(2 * kp + 1) * 512 + h * 64 + n];
        __nv_bfloat162 p2 = __floats2bfloat162_rn(w0, w1);
        Bs32[kp * LDBP + n] = *(unsigned int*)&p2;
    }
    // Load A: bf16 rows of g_h0h, 2 threads per row, 4 uint4 each
    {
        int r = tid >> 1, half = tid & 1;
        int row = m0 + r;
        if (row < N_NODES) {
            const uint4* src = (const uint4*)&g_h0h[row * 32 + half * 16];
            #pragma unroll
            for (int q = 0; q < 4; q++) {
                uint4 v = src[q];
                int p = half * 16 + q * 4;
                As32[r * LDAP + p + 0] = v.x;
                As32[r * LDAP + p + 1] = v.y;
                As32[r * LDAP + p + 2] = v.z;
                As32[r * LDAP + p + 3] = v.w;
            }
        } else {
            #pragma unroll
            for (int q = 0; q < 16; q++) As32[r * LDAP + half * 16 + q] = 0u;
        }
    }
    __syncthreads();

    const int wid = tid >> 5, lane = tid & 31;
    const int mW = (wid >> 1) * 32, nW = (wid & 1) * 32;
    const int g = lane >> 2, tg = lane & 3;

    float c[2][4][4] = {};
    #pragma unroll
    for (int kq = 0; kq < 4; kq++) {   // 16 k per step
        int kp0 = kq * 8;
        unsigned int a[2][4], b[4][2];
        #pragma unroll
        for (int mi = 0; mi < 2; mi++) {
            int r0 = mW + mi * 16 + g;
            a[mi][0] = As32[(r0)     * LDAP + kp0 + tg];
            a[mi][1] = As32[(r0 + 8) * LDAP + kp0 + tg];
            a[mi][2] = As32[(r0)     * LDAP + kp0 + tg + 4];
            a[mi][3] = As32[(r0 + 8) * LDAP + kp0 + tg + 4];
        }
        #pragma unroll
        for (int ni = 0; ni < 4; ni++) {
            int cn = nW + ni * 8 + g;
            b[ni][0] = Bs32[(kp0 + tg)     * LDBP + cn];
            b[ni][1] = Bs32[(kp0 + tg + 4) * LDBP + cn];
        }
        #pragma unroll
        for (int mi = 0; mi < 2; mi++)
            #pragma unroll
            for (int ni = 0; ni < 4; ni++) mma_bf16(c[mi][ni], a[mi], b[ni]);
    }
    __syncthreads();

    // store C tile to smem (overlays As/Bs)
    #pragma unroll
    for (int mi = 0; mi < 2; mi++) {
        int rA = mW + mi * 16 + g;
        #pragma unroll
        for (int ni = 0; ni < 4; ni++) {
            int c0 = nW + ni * 8 + tg * 2;
            *(float2*)&Cs[(rA)     * LDC + c0] = make_float2(c[mi][ni][0], c[mi][ni][1]);
            *(float2*)&Cs[(rA + 8) * LDC + c0] = make_float2(c[mi][ni][2], c[mi][ni][3]);
        }
    }
    __syncthreads();

    // epilogue: 2 threads per row; bf16 pack + per-head att dots
    {
        int r = tid >> 1, half = tid & 1;
        int row = m0 + r;
        int cb = half * 32;
        float ps = 0.f, pd = 0.f;
        if (row < N_NODES) {
            #pragma unroll
            for (int q = 0; q < 4; q++) {       // 4 x uint4 (8 bf16 each)
                union { __nv_bfloat162 h2[4]; uint4 u; } pk;
                #pragma unroll
                for (int e = 0; e < 4; e++) {
                    float v0 = Cs[r * LDC + cb + q * 8 + 2 * e];
                    float v1 = Cs[r * LDC + cb + q * 8 + 2 * e + 1];
                    pk.h2[e] = __floats2bfloat162_rn(v0, v1);
                    ps += v0 * sAs[cb + q * 8 + 2 * e] + v1 * sAs[cb + q * 8 + 2 * e + 1];
                    pd += v0 * sAd[cb + q * 8 + 2 * e] + v1 * sAd[cb + q * 8 + 2 * e + 1];
                }
                *(uint4*)&g_xh[(size_t)row * 512 + h * 64 + cb + q * 8] = pk.u;
            }
        }
        ps += __shfl_xor_sync(0xffffffffu, ps, 1);
        pd += __shfl_xor_sync(0xffffffffu, pd, 1);
        if (half == 0 && row < N_NODES) {
            g_as[row * 8 + h] = ps;
            g_ad[row * 8 + h] = pd;
        }
    }
}

// ---------------- CSR build (by dst, incl. self-loops) ----------------
__global__ void k_hist(const void* ei) {
    int base = blockIdx.x * 1024 + threadIdx.x;
    int is64 = g_is64[0];
    #pragma unroll
    for (int u = 0; u < 4; u++) {
        int e = base + u * 256;
        if (e < E_EDGES) {
            int dst = ld_idx(ei, (long)E_EDGES + e, is64);
            atomicAdd(&g_off[dst + 1], 1);
        }
    }
}

// Phase A: per-block local inclusive scan of (deg + 1); block totals to g_chainv.
__global__ void k_scanA() {
    int b = blockIdx.x, t = threadIdx.x;
    int i = b * 1024 + t;
    int v = (i < N_NODES) ? (g_off[i + 1] + 1) : 0;
    int lane = t & 31, w = t >> 5;
    int x = v;
    #pragma unroll
    for (int d = 1; d < 32; d <<= 1) {
        int y = __shfl_up_sync(0xffffffffu, x, d);
        if (lane >= d) x += y;
    }
    __shared__ int wsum[32];
    if (lane == 31) wsum[w] = x;
    __syncthreads();
    if (w == 0) {
        int y = wsum[lane];
        #pragma unroll
        for (int d = 1; d < 32; d <<= 1) {
            int z = __shfl_up_sync(0xffffffffu, y, d);
            if (lane >= d) y += z;
        }
        wsum[lane] = y;
    }
    __syncthreads();
    int incl = x + (w > 0 ? wsum[w - 1] : 0);
    if (t == 1023) g_chainv[b] = incl;
    if (i < N_NODES) {
        g_off[i + 1] = incl;   // block-local inclusive, base added in phase C
        g_pos[i] = v;          // stash deg+1
    }
}

// Phase B: one warp turns block totals into exclusive bases.
__global__ void k_scanB() {
    int t = threadIdx.x;  // 32
    int v = (t < SCAN_BLKS) ? g_chainv[t] : 0;
    int x = v;
    #pragma unroll
    for (int d = 1; d < 32; d <<= 1) {
        int y = __shfl_up_sync(0xffffffffu, x, d);
        if (t >= d) x += y;
    }
    if (t < SCAN_BLKS) g_chainv[t] = x - v;  // exclusive base
}

// Phase C: add base, finalize g_off (inclusive) and g_pos (exclusive start).
__global__ void k_scanC() {
    int b = blockIdx.x, t = threadIdx.x;
    int i = b * 1024 + t;
    if (i < N_NODES) {
        int base = g_chainv[b];
        int f = g_off[i + 1] + base;
        g_off[i + 1] = f;
        g_pos[i] = f - g_pos[i];
    }
}

__global__ void k_scatter(const void* ei) {
    int t = blockIdx.x * 256 + threadIdx.x;
    int is64 = g_is64[0];
    if (t < E_EDGES) {
        int src = ld_idx(ei, t, is64);
        int dst = ld_idx(ei, (long)E_EDGES + t, is64);
        int slot = atomicAdd(&g_pos[dst], 1);
        g_esrc[slot] = src;
    } else if (t < E_EDGES + N_NODES) {
        int n = t - E_EDGES;
        int slot = atomicAdd(&g_pos[n], 1);
        g_esrc[slot] = n;  // self-loop
    }
}

// ---------------- per-dst online softmax + aggregation (bf16 gather, bf16 out) --------
__global__ void k_agg(const float* __restrict__ bg) {
    int nid = blockIdx.x;
    int tid = threadIdx.x;
    int h = tid >> 3, cg = tid & 7;
    float adh = g_ad[nid * 8 + h];
    int beg = g_off[nid], end = g_off[nid + 1];
    float m = NEG_INF, s = 0.f;
    float a[8] = {};
    const uint4* xh4 = (const uint4*)g_xh;
    int lane_off = h * 8 + cg;

    int src = g_esrc[beg];
    float asv = g_as[src * 8 + h];
    uint4 cvu = xh4[(size_t)src * 64 + lane_off];
    for (int j = beg; j < end; j++) {
        float asn = 0.f; uint4 cvn = make_uint4(0, 0, 0, 0);
        if (j + 1 < end) {
            int srcn = g_esrc[j + 1];
            asn = g_as[srcn * 8 + h];
            cvn = xh4[(size_t)srcn * 64 + lane_off];
        }
        float e = asv + adh;
        e = (e > 0.f) ? e : 0.2f * e;
        float mn = fmaxf(m, e);
        float wo = __expf(m - mn);
        float we = __expf(e - mn);
        union { uint4 u; __nv_bfloat162 h2[4]; } cv;
        cv.u = cvu;
        s = s * wo + we;
        #pragma unroll
        for (int q = 0; q < 4; q++) {
            float2 f = __bfloat1622float2(cv.h2[q]);
            a[2 * q]     = a[2 * q]     * wo + we * f.x;
            a[2 * q + 1] = a[2 * q + 1] * wo + we * f.y;
        }
        m = mn;
        asv = asn; cvu = cvn;
    }
    float inv = 1.f / s;
    int c0 = h * 64 + cg * 8;
    const float4 bg0 = *(const float4*)&bg[c0];
    const float4 bg1 = *(const float4*)&bg[c0 + 4];
    union { __nv_bfloat162 h2[4]; uint4 u; } pk;
    pk.h2[0] = __floats2bfloat162_rn(fmaxf(a[0] * inv + bg0.x, 0.f),
                                     fmaxf(a[1] * inv + bg0.y, 0.f));
    pk.h2[1] = __floats2bfloat162_rn(fmaxf(a[2] * inv + bg0.z, 0.f),
                                     fmaxf(a[3] * inv + bg0.w, 0.f));
    pk.h2[2] = __floats2bfloat162_rn(fmaxf(a[4] * inv + bg1.x, 0.f),
                                     fmaxf(a[5] * inv + bg1.y, 0.f));
    pk.h2[3] = __floats2bfloat162_rn(fmaxf(a[6] * inv + bg1.z, 0.f),
                                     fmaxf(a[7] * inv + bg1.w, 0.f));
    *(uint4*)&g_aggrh[(size_t)nid * 512 + c0] = pk.u;
}

// ---------------- out = relu(aggr @ Wh + bh), bf16 mma m16n8k16. M=20000 N=64 K=512 ----
__global__ void k_gemm_out(const float* __restrict__ Wh, const float* __restrict__ bh) {
    const int m0 = blockIdx.x * 64;
    const int tid = threadIdx.x;
    __shared__ unsigned int As32[64 * LDAP];   // 64 rows x 32 bf16-pairs
    __shared__ unsigned int Bs32[32 * LDBP];   // 32 k-pairs x 64 cols
    const int wid = tid >> 5, lane = tid & 31;
    const int mW = (wid >> 1) * 32, nW = (wid & 1) * 32;
    const int g = lane >> 2, tg = lane & 3;
    float c[2][4][4] = {};

    for (int kk = 0; kk < 512; kk += 64) {
        {   // load A 64x64 bf16 chunk
            int r = tid >> 1, half = tid & 1;
            int row = m0 + r;
            if (row < N_NODES) {
                const uint4* src = (const uint4*)&g_aggrh[(size_t)row * 512 + kk + half * 32];
                #pragma unroll
                for (int q = 0; q < 4; q++) {
                    uint4 v = src[q];
                    int p = half * 16 + q * 4;
                    As32[r * LDAP + p + 0] = v.x;
                    As32[r * LDAP + p + 1] = v.y;
                    As32[r * LDAP + p + 2] = v.z;
                    As32[r * LDAP + p + 3] = v.w;
                }
            } else {
                #pragma unroll
                for (int q = 0; q < 16; q++) As32[r * LDAP + half * 16 + q] = 0u;
            }
        }
        #pragma unroll
        for (int l = 0; l < 16; l++) {   // load B 64x64 chunk as k-pairs
            int lin = l * 128 + tid;
            int kp = lin >> 6, n = lin & 63;
            float w0 = Wh[(kk + 2 * kp) * 64 + n];
            float w1 = Wh[(kk + 2 * kp + 1) * 64 + n];
            __nv_bfloat162 p2 = __floats2bfloat162_rn(w0, w1);
            Bs32[kp * LDBP + n] = *(unsigned int*)&p2;
        }
        __syncthreads();
        #pragma unroll
        for (int kq = 0; kq < 4; kq++) {    // 16 k per iter
            int kp0 = kq * 8;
            unsigned int a[2][4], b[4][2];
            #pragma unroll
            for (int mi = 0; mi < 2; mi++) {
                int r0 = mW + mi * 16 + g;
                a[mi][0] = As32[(r0)     * LDAP + kp0 + tg];
                a[mi][1] = As32[(r0 + 8) * LDAP + kp0 + tg];
                a[mi][2] = As32[(r0)     * LDAP + kp0 + tg + 4];
                a[mi][3] = As32[(r0 + 8) * LDAP + kp0 + tg + 4];
            }
            #pragma unroll
            for (int ni = 0; ni < 4; ni++) {
                int cn = nW + ni * 8 + g;
                b[ni][0] = Bs32[(kp0 + tg)     * LDBP + cn];
                b[ni][1] = Bs32[(kp0 + tg + 4) * LDBP + cn];
            }
            #pragma unroll
            for (int mi = 0; mi < 2; mi++)
                #pragma unroll
                for (int ni = 0; ni < 4; ni++) mma_bf16(c[mi][ni], a[mi], b[ni]);
        }
        __syncthreads();
    }

    float2 bh2[4];
    #pragma unroll
    for (int ni = 0; ni < 4; ni++) bh2[ni] = *(const float2*)&bh[nW + ni * 8 + tg * 2];
    #pragma unroll
    for (int mi = 0; mi < 2; mi++) {
        int rA = m0 + mW + mi * 16 + g;
        #pragma unroll
        for (int ni = 0; ni < 4; ni++) {
            int col = nW + ni * 8 + tg * 2;
            if (rA < N_NODES) {
                float2 o = make_float2(fmaxf(c[mi][ni][0] + bh2[ni].x, 0.f),
                                       fmaxf(c[mi][ni][1] + bh2[ni].y, 0.f));
                *(float2*)&g_out[rA * 64 + col] = o;
            }
            if (rA + 8 < N_NODES) {
                float2 o = make_float2(fmaxf(c[mi][ni][2] + bh2[ni].x, 0.f),
                                       fmaxf(c[mi][ni][3] + bh2[ni].y, 0.f));
                *(float2*)&g_out[(rA + 8) * 64 + col] = o;
            }
        }
    }
}

__device__ __forceinline__ float sigmoidf_(float x) { return 1.f / (1.f + __expf(-x)); }

// ---------------- fused Set2Set (3 steps) + final MLP; warp-per-node attention --------
__global__ void k_s2s(const void* bt,
                      const float* __restrict__ W_ih, const float* __restrict__ W_hh,
                      const float* __restrict__ b_ih, const float* __restrict__ b_hh,
                      const float* __restrict__ W1, const float* __restrict__ b1,
                      const float* __restrict__ W2, const float* __restrict__ b2,
                      float* __restrict__ out) {
    int b = blockIdx.x, tid = threadIdx.x;
    int warp = tid >> 5, lane = tid & 31;
    __shared__ float sq[128], sh[64], sc[64], gsh[256];
    __shared__ float wm_[8], ws_[8], wr_[8][64];
    __shared__ float fin[2];
    __shared__ int sbnd[2];
    if (tid < 2) {
        int target = b + tid;
        int is64 = g_is64[1];
        int lo = 0, hi = N_NODES;
        while (lo < hi) {
            int mid = (lo + hi) >> 1;
            int v = ld_idx(bt, mid, is64);
            if (v < target) lo = mid + 1; else hi = mid;
        }
        sbnd[tid] = lo;
    }
    if (tid < 128) sq[tid] = 0.f;
    if (tid < 64) { sh[tid] = 0.f; sc[tid] = 0.f; }
    __syncthreads();
    int beg = sbnd[0], end = sbnd[1];

    for (int step = 0; step < 3; step++) {
        // ---- LSTM cell ----
        float acc = b_ih[tid] + b_hh[tid];
        const float* wi = &W_ih[tid * 128];
        #pragma unroll 4
        for (int k = 0; k < 128; k++) acc += sq[k] * wi[k];
        const float* wh = &W_hh[tid * 64];
        #pragma unroll 4
        for (int k = 0; k < 64; k++) acc += sh[k] * wh[k];
        gsh[tid] = acc;
        __syncthreads();
        if (tid < 64) {
            float ig = sigmoidf_(gsh[tid]);
            float fg = sigmoidf_(gsh[64 + tid]);
            float gg = tanhf(gsh[128 + tid]);
            float og = sigmoidf_(gsh[192 + tid]);
            float cv = fg * sc[tid] + ig * gg;
            sc[tid] = cv;
            sh[tid] = og * tanhf(cv);
        }
        __syncthreads();
        // ---- attention, warp-per-node, no block sync in loop ----
        float2 q2 = *(const float2*)&sh[2 * lane];
        float m = NEG_INF, s = 0.f;
        float2 r2 = make_float2(0.f, 0.f);
        int i = beg + warp;
        float2 v = (i < end) ? *(const float2*)&g_out[(size_t)i * 64 + 2 * lane]
                             : make_float2(0.f, 0.f);
        for (; i < end; i += 8) {
            int inext = i + 8;
            float2 vn = (inext < end) ? *(const float2*)&g_out[(size_t)inext * 64 + 2 * lane]
                                      : make_float2(0.f, 0.f);
            float p = v.x * q2.x + v.y * q2.y;
            #pragma unroll
            for (int off = 16; off; off >>= 1) p += __shfl_xor_sync(0xffffffffu, p, off);
            float mn = fmaxf(m, p);
            float wo = __expf(m - mn);
            float we = __expf(p - mn);
            s = s * wo + we;
            r2.x = r2.x * wo + we * v.x;
            r2.y = r2.y * wo + we * v.y;
            m = mn;
            v = vn;
        }
        if (lane == 0) { wm_[warp] = m; ws_[warp] = s; }
        wr_[warp][2 * lane] = r2.x;
        wr_[warp][2 * lane + 1] = r2.y;
        __syncthreads();
        if (tid < 64) {
            float M = NEG_INF;
            #pragma unroll
            for (int w = 0; w < 8; w++) M = fmaxf(M, wm_[w]);
            float S = 0.f, R = 0.f;
            #pragma unroll
            for (int w = 0; w < 8; w++) {
                float f = (wm_[w] == NEG_INF) ? 0.f : __expf(wm_[w] - M);
                S += ws_[w] * f;
                R += wr_[w][tid] * f;
            }
            float r = (S > 0.f) ? (R / S) : 0.f;
            sq[tid] = sh[tid];
            sq[64 + tid] = r;
        }
        __syncthreads();
    }
    // ---- final MLP ----
    if (tid < 64) {
        float acc = b1[tid];
        #pragma unroll 4
        for (int k = 0; k < 128; k++) acc += sq[k] * W1[k * 64 + tid];
        acc = fmaxf(acc, 0.f);
        float z = acc * W2[tid];
        #pragma unroll
        for (int off = 16; off; off >>= 1) z += __shfl_down_sync(0xffffffffu, z, off);
        if ((tid & 31) == 0) fin[tid >> 5] = z;
    }
    __syncthreads();
    if (tid == 0) out[b] = fin[0] + fin[1] + b2[0];
}

// ---------------- orchestration: two-stream fork (CSR build || feature GEMMs) --------
extern "C" void kernel_launch(void* const* d_in, const int* in_sizes, int n_in,
                              void* d_out, int out_size) {
    const float* x   = (const float*)d_in[0];
    const void*  ei  = d_in[1];
    const void*  bt  = d_in[2];
    const float* W0  = (const float*)d_in[3];
    const float* b0  = (const float*)d_in[4];
    const float* Wg  = (const float*)d_in[5];
    const float* asr = (const float*)d_in[6];
    const float* ads = (const float*)d_in[7];
    const float* bg  = (const float*)d_in[8];
    const float* Wh  = (const float*)d_in[9];
    const float* bh  = (const float*)d_in[10];
    const float* Wih = (const float*)d_in[11];
    const float* Whh = (const float*)d_in[12];
    const float* bih = (const float*)d_in[13];
    const float* bhh = (const float*)d_in[14];
    const float* W1  = (const float*)d_in[15];
    const float* b1  = (const float*)d_in[16];
    const float* W2  = (const float*)d_in[17];
    const float* b2  = (const float*)d_in[18];
    float* out = (float*)d_out;

    static cudaStream_t s1 = nullptr, s2 = nullptr;
    static cudaEvent_t evA = nullptr, evB = nullptr, evC = nullptr;
    if (s1 == nullptr) {
        cudaStreamCreateWithFlags(&s1, cudaStreamNonBlocking);
        cudaStreamCreateWithFlags(&s2, cudaStreamNonBlocking);
        cudaEventCreateWithFlags(&evA, cudaEventDisableTiming);
        cudaEventCreateWithFlags(&evB, cudaEventDisableTiming);
        cudaEventCreateWithFlags(&evC, cudaEventDisableTiming);
    }

    void* off_ptr = nullptr;
    cudaGetSymbolAddress(&off_ptr, g_off);

    k_detect<<<1, 256>>>((const int*)ei, (const int*)bt);
    cudaEventRecord(evA, 0);
    cudaStreamWaitEvent(s1, evA, 0);
    cudaStreamWaitEvent(s2, evA, 0);

    // branch 1: feature path
    k_lin0<<<(N_NODES * 32 + 255) / 256, 256, 0, s1>>>(x, W0, b0);
    k_gemm_xh<<<dim3(8, (N_NODES + 127) / 128), 256, 0, s1>>>(Wg, asr, ads);
    cudaEventRecord(evB, s1);

    // branch 2: CSR build
    cudaMemsetAsync(off_ptr, 0, (N_NODES + 1) * sizeof(int), s2);
    k_hist<<<(E_EDGES + 1023) / 1024, 256, 0, s2>>>(ei);
    k_scanA<<<SCAN_BLKS, 1024, 0, s2>>>();
    k_scanB<<<1, 32, 0, s2>>>();
    k_scanC<<<SCAN_BLKS, 1024, 0, s2>>>();
    k_scatter<<<(E_EDGES + N_NODES + 255) / 256, 256, 0, s2>>>(ei);
    cudaEventRecord(evC, s2);

    // join
    cudaStreamWaitEvent(0, evB, 0);
    cudaStreamWaitEvent(0, evC, 0);

    k_agg<<<N_NODES, 64>>>(bg);
    k_gemm_out<<<(N_NODES + 63) / 64, 128>>>(Wh, bh);
    k_s2s<<<B_BATCH, 256>>>(bt, Wih, Whh, bih, bhh, W1, b1, W2, b2, out);
}